// round 1
// baseline (speedup 1.0000x reference)
#include <cuda_runtime.h>

#define N_NODES 10000
#define N_EDGES 160000
#define F_NODE  128
#define C_GCN   64
#define S_SEQ   32
#define T_SEQ   96
#define H       128
#define G4      512
#define MP      68
#define NBLK    148
#define NPAD    (NBLK*MP)     /* 10064 */
#define THREADS 256
#define K0      160           /* 128 h0 + 32 seq */
#define K1      256           /* 128 h1 + 128 h0 */

// ---------------- scratch (zero-initialized device globals) ----------------
__device__ int   g_i32;                          // 1 => edge_index is int32
__device__ float g_deg [N_NODES];
__device__ float g_xwS [N_NODES*C_GCN];
__device__ float g_acc [N_NODES*C_GCN];
__device__ float g_gcnT[C_GCN*N_NODES];
__device__ float g_gpartT[(size_t)G4*NPAD];      // pad region stays 0
__device__ float g_W0  [G4*K0];
__device__ float g_W1  [G4*K1];
__device__ float g_b1  [G4];

__device__ __forceinline__ int eidx(const void* ei, int idx){
  if (g_i32) return ((const int*)ei)[idx];
  return (int)((const long long*)ei)[idx];
}

// ---------------- GCN + prep kernels ----------------
__global__ void k_reset(){ g_i32 = 0; }

__global__ void k_detect(const int* ei){
  int any = 0;
  for (int i = blockIdx.x*blockDim.x + threadIdx.x; i < N_EDGES; i += gridDim.x*blockDim.x)
    any |= ei[2*i+1];
  if (__syncthreads_or(any)) { if (threadIdx.x == 0) atomicOr(&g_i32, 1); }
}

__global__ void k_init(){
  int i = blockIdx.x*blockDim.x + threadIdx.x;
  if (i < N_NODES*C_GCN){
    g_acc[i] = 0.f;
    if (i < N_NODES) g_deg[i] = 1.f;   // self loop
  }
}

__global__ void k_degedge(const void* ei){
  int e = blockIdx.x*blockDim.x + threadIdx.x;
  if (e < N_EDGES) atomicAdd(&g_deg[eidx(ei, N_EDGES + e)], 1.f);
}

__global__ void k_xw(const float* __restrict__ nf, const float* __restrict__ gw){
  int idx = blockIdx.x*blockDim.x + threadIdx.x;
  if (idx >= N_NODES*C_GCN) return;
  int n = idx >> 6, c = idx & 63;
  float s = 0.f;
  #pragma unroll 8
  for (int k = 0; k < F_NODE; k++) s += nf[n*F_NODE + k] * __ldg(&gw[k*C_GCN + c]);
  g_xwS[idx] = s * rsqrtf(g_deg[n]);
}

__global__ void k_scatter(const void* ei){
  int idx = blockIdx.x*blockDim.x + threadIdx.x;
  if (idx >= N_EDGES*64) return;
  int e = idx >> 6, c = idx & 63;
  int r   = eidx(ei, e);
  int col = eidx(ei, N_EDGES + e);
  atomicAdd(&g_acc[col*64 + c], g_xwS[r*64 + c]);
}

__global__ void k_gcnT(const float* __restrict__ gb){
  int idx = blockIdx.x*blockDim.x + threadIdx.x;
  if (idx >= N_NODES*C_GCN) return;
  int n = idx >> 6, c = idx & 63;
  // out = dinv[n]*(sum_edges xwS[row] + xwS[n]) + b    (self loop folded in)
  float v = rsqrtf(g_deg[n]) * (g_acc[idx] + g_xwS[idx]) + __ldg(&gb[c]);
  g_gcnT[c*N_NODES + n] = v;
}

__global__ void k_gpartT(const float* __restrict__ wih0, const float* __restrict__ bih0,
                         const float* __restrict__ bhh0){
  int n = blockIdx.x*blockDim.x + threadIdx.x;
  int g = blockIdx.y;
  if (n >= N_NODES) return;
  float s = __ldg(&bih0[g]) + __ldg(&bhh0[g]);
  #pragma unroll 8
  for (int j = 0; j < C_GCN; j++)
    s += g_gcnT[j*N_NODES + n] * __ldg(&wih0[g*96 + 32 + j]);
  g_gpartT[(size_t)g*NPAD + n] = s;
}

__global__ void k_wcat(const float* wih0, const float* whh0, const float* wih1, const float* whh1,
                       const float* bih1, const float* bhh1){
  int idx = blockIdx.x*blockDim.x + threadIdx.x;
  if (idx < G4*K1){
    int g = idx / K1, k = idx - g*K1;
    g_W1[idx] = (k < H) ? whh1[g*H + k] : wih1[g*H + (k - H)];
  }
  if (idx < G4*K0){
    int g = idx / K0, k = idx - g*K0;
    g_W0[idx] = (k < H) ? whh0[g*H + k] : wih0[g*96 + (k - H)];
  }
  if (idx < G4) g_b1[idx] = bih1[idx] + bhh1[idx];
}

// ---------------- mega kernel (fused 2-layer LSTM over T) ----------------
__device__ __forceinline__ unsigned long long fma2(unsigned long long a, unsigned long long b,
                                                   unsigned long long c){
  unsigned long long d;
  asm("fma.rn.f32x2 %0, %1, %2, %3;" : "=l"(d) : "l"(a), "l"(b), "l"(c));
  return d;
}
__device__ __forceinline__ unsigned long long pk2(float a, float b){
  unsigned long long r;
  asm("mov.b64 %0, {%1, %2};" : "=l"(r) : "f"(a), "f"(b));
  return r;
}
__device__ __forceinline__ float sig_f(float x){
  return __fdividef(1.f, 1.f + __expf(-x));
}
__device__ __forceinline__ float tanh_f(float x){
  float ax = fminf(fabsf(x), 15.f);
  float e  = __expf(2.f*ax);
  float r  = 1.f - __fdividef(2.f, e + 1.f);
  return copysignf(r, x);
}

// C[512 x MP] = W[512 x K] * A[K x MP] (+init); A is k-major in smem.
template<int K, bool GP>
__device__ __forceinline__ void gemm_phase(const float* __restrict__ A, const float* __restrict__ W,
                                           const float* __restrict__ initv, int base,
                                           float* __restrict__ gbuf, int tid){
  for (int task = tid; task < 64*17; task += THREADS){
    int jt = task / 17, mt = task - jt*17;
    int j0 = jt*8, m0 = mt*4;
    unsigned long long acc[8][2];
    #pragma unroll
    for (int jj = 0; jj < 8; jj++){
      if (GP){
        const float* p = initv + (size_t)(j0+jj)*NPAD + base + m0;
        acc[jj][0] = pk2(p[0], p[1]);
        acc[jj][1] = pk2(p[2], p[3]);
      } else {
        float b = __ldg(&initv[j0+jj]);
        acc[jj][0] = pk2(b, b);
        acc[jj][1] = acc[jj][0];
      }
    }
    #pragma unroll 2
    for (int k = 0; k < K; k += 4){
      float4 av[4];
      #pragma unroll
      for (int kk = 0; kk < 4; kk++) av[kk] = *(const float4*)(A + (k+kk)*MP + m0);
      const unsigned long long* avp = (const unsigned long long*)av;
      #pragma unroll
      for (int jj = 0; jj < 8; jj++){
        float4 wv = __ldg((const float4*)(W + (j0+jj)*K + k));
        float wf0 = wv.x, wf1 = wv.y, wf2 = wv.z, wf3 = wv.w;
        unsigned long long w0 = pk2(wf0, wf0);
        acc[jj][0] = fma2(avp[0], w0, acc[jj][0]);
        acc[jj][1] = fma2(avp[1], w0, acc[jj][1]);
        unsigned long long w1 = pk2(wf1, wf1);
        acc[jj][0] = fma2(avp[2], w1, acc[jj][0]);
        acc[jj][1] = fma2(avp[3], w1, acc[jj][1]);
        unsigned long long w2 = pk2(wf2, wf2);
        acc[jj][0] = fma2(avp[4], w2, acc[jj][0]);
        acc[jj][1] = fma2(avp[5], w2, acc[jj][1]);
        unsigned long long w3 = pk2(wf3, wf3);
        acc[jj][0] = fma2(avp[6], w3, acc[jj][0]);
        acc[jj][1] = fma2(avp[7], w3, acc[jj][1]);
      }
    }
    #pragma unroll
    for (int jj = 0; jj < 8; jj++){
      float2 lo = *(float2*)&acc[jj][0];
      float2 hi = *(float2*)&acc[jj][1];
      *(float4*)(gbuf + (j0+jj)*MP + m0) = make_float4(lo.x, lo.y, hi.x, hi.y);
    }
  }
}

__global__ void __launch_bounds__(THREADS, 1)
k_mega(const float* __restrict__ seq, const float* __restrict__ fcw,
       const float* __restrict__ fcb, float* __restrict__ out){
  extern __shared__ float sm[];
  float* h1   = sm;                        // [128][MP]   (A1 rows 0..127)
  float* h0   = sm + H*MP;                 // [128][MP]   (A1 rows 128..255; A0 rows 0..127)
  float* sq   = sm + 2*H*MP;               // [32][MP]    (A0 rows 128..159)
  float* gbuf = sm + (2*H + S_SEQ)*MP;     // [512][MP]
  const float* A1 = h1;
  const float* A0 = h0;

  int tid  = threadIdx.x;
  int base = blockIdx.x * MP;

  for (int i = tid; i < (2*H + S_SEQ)*MP; i += THREADS) sm[i] = 0.f;
  float c0r[34], c1r[34];
  #pragma unroll
  for (int i = 0; i < 34; i++){ c0r[i] = 0.f; c1r[i] = 0.f; }
  __syncthreads();

  for (int t = 0; t < T_SEQ; t++){
    // stage seq_t transposed: sq[i][m]
    for (int idx = tid; idx < S_SEQ*MP; idx += THREADS){
      int m = idx >> 5, i = idx & 31;
      int n = base + m; n = (n < N_NODES) ? n : (N_NODES - 1);
      sq[i*MP + m] = seq[(size_t)n*(T_SEQ*S_SEQ) + t*S_SEQ + i];
    }
    __syncthreads();

    gemm_phase<K0, true >(A0, g_W0, g_gpartT, base, gbuf, tid);
    __syncthreads();
    #pragma unroll
    for (int it = 0; it < 34; it++){
      int idx = it*THREADS + tid;
      int j = idx / MP, m = idx - j*MP;
      float gi = gbuf[j*MP + m];
      float gf = gbuf[(j+128)*MP + m];
      float gz = gbuf[(j+256)*MP + m];
      float go = gbuf[(j+384)*MP + m];
      float c  = sig_f(gf)*c0r[it] + sig_f(gi)*tanh_f(gz);
      c0r[it]  = c;
      h0[j*MP + m] = sig_f(go)*tanh_f(c);
    }
    __syncthreads();

    gemm_phase<K1, false>(A1, g_W1, g_b1, base, gbuf, tid);
    __syncthreads();
    #pragma unroll
    for (int it = 0; it < 34; it++){
      int idx = it*THREADS + tid;
      int j = idx / MP, m = idx - j*MP;
      float gi = gbuf[j*MP + m];
      float gf = gbuf[(j+128)*MP + m];
      float gz = gbuf[(j+256)*MP + m];
      float go = gbuf[(j+384)*MP + m];
      float c  = sig_f(gf)*c1r[it] + sig_f(gi)*tanh_f(gz);
      c1r[it]  = c;
      h1[j*MP + m] = sig_f(go)*tanh_f(c);
    }
    __syncthreads();
  }

  float fb = __ldg(fcb);
  for (int m = tid; m < MP; m += THREADS){
    int n = base + m;
    if (n < N_NODES){
      float s = fb;
      #pragma unroll 16
      for (int j = 0; j < H; j++) s += h1[j*MP + m] * __ldg(&fcw[j]);
      out[n] = s;
    }
  }
}

// ---------------- launch ----------------
extern "C" void kernel_launch(void* const* d_in, const int* in_sizes, int n_in,
                              void* d_out, int out_size){
  const float* seq  = (const float*)d_in[0];
  const void*  ei   = d_in[1];
  const float* nf   = (const float*)d_in[3];
  const float* gw   = (const float*)d_in[5];
  const float* gb   = (const float*)d_in[6];
  const float* wih0 = (const float*)d_in[7];
  const float* whh0 = (const float*)d_in[8];
  const float* bih0 = (const float*)d_in[9];
  const float* bhh0 = (const float*)d_in[10];
  const float* wih1 = (const float*)d_in[11];
  const float* whh1 = (const float*)d_in[12];
  const float* bih1 = (const float*)d_in[13];
  const float* bhh1 = (const float*)d_in[14];
  const float* fcw  = (const float*)d_in[15];
  const float* fcb  = (const float*)d_in[16];
  float* out = (float*)d_out;

  k_reset<<<1,1>>>();
  k_detect<<<64,256>>>((const int*)ei);
  k_init<<<(N_NODES*C_GCN + 255)/256, 256>>>();
  k_degedge<<<(N_EDGES + 255)/256, 256>>>(ei);
  k_xw<<<(N_NODES*C_GCN + 255)/256, 256>>>(nf, gw);
  k_scatter<<<(N_EDGES*64 + 255)/256, 256>>>(ei);
  k_gcnT<<<(N_NODES*C_GCN + 255)/256, 256>>>(gb);
  dim3 gp((N_NODES + 255)/256, G4);
  k_gpartT<<<gp, 256>>>(wih0, bih0, bhh0);
  k_wcat<<<(G4*K1 + 255)/256, 256>>>(wih0, whh0, wih1, whh1, bih1, bhh1);

  size_t smem = (size_t)(2*H + S_SEQ + G4)*MP*sizeof(float);   // 217600 B
  cudaFuncSetAttribute(k_mega, cudaFuncAttributeMaxDynamicSharedMemorySize, (int)smem);
  k_mega<<<NBLK, THREADS, smem>>>(seq, fcw, fcb, out);
}

// round 2
// speedup vs baseline: 1.8033x; 1.8033x over previous
#include <cuda_runtime.h>

#define N_NODES 10000
#define N_EDGES 160000
#define F_NODE  128
#define C_GCN   64
#define S_SEQ   32
#define T_SEQ   96
#define H       128
#define G4      512
#define MP      72
#define NBLK    148
#define NPAD    (NBLK*MP)     /* 10656 */
#define THREADS 256
#define PAIRS   18            /* 36 nodes per thread as f32x2 pairs */

// ---------------- scratch (zero-initialized device globals) ----------------
__device__ int   g_i32;                          // 1 => edge_index is int32
__device__ float g_deg [N_NODES];
__device__ float g_xwS [N_NODES*C_GCN];
__device__ float g_acc [N_NODES*C_GCN];
__device__ float g_gcnT[C_GCN*N_NODES];
__device__ float g_gpart[(size_t)G4*NPAD];       // pad region stays 0
__device__ float g_W0  [160*G4];                 // k-major [k][s][4]
__device__ float g_W1  [256*G4];
__device__ float g_b1  [G4];

__device__ __forceinline__ int eidx(const void* ei, int idx){
  if (g_i32) return ((const int*)ei)[idx];
  return (int)((const long long*)ei)[idx];
}

// ---------------- GCN + prep kernels ----------------
__global__ void k_reset(){ g_i32 = 0; }

__global__ void k_detect(const int* ei){
  int any = 0;
  for (int i = blockIdx.x*blockDim.x + threadIdx.x; i < N_EDGES; i += gridDim.x*blockDim.x)
    any |= ei[2*i+1];
  if (__syncthreads_or(any)) { if (threadIdx.x == 0) atomicOr(&g_i32, 1); }
}

__global__ void k_init(){
  int i = blockIdx.x*blockDim.x + threadIdx.x;
  if (i < N_NODES*C_GCN){
    g_acc[i] = 0.f;
    if (i < N_NODES) g_deg[i] = 1.f;   // self loop
  }
}

__global__ void k_degedge(const void* ei){
  int e = blockIdx.x*blockDim.x + threadIdx.x;
  if (e < N_EDGES) atomicAdd(&g_deg[eidx(ei, N_EDGES + e)], 1.f);
}

__global__ void k_xw(const float* __restrict__ nf, const float* __restrict__ gw){
  int idx = blockIdx.x*blockDim.x + threadIdx.x;
  if (idx >= N_NODES*C_GCN) return;
  int n = idx >> 6, c = idx & 63;
  float s = 0.f;
  #pragma unroll 8
  for (int k = 0; k < F_NODE; k++) s += nf[n*F_NODE + k] * __ldg(&gw[k*C_GCN + c]);
  g_xwS[idx] = s * rsqrtf(g_deg[n]);
}

__global__ void k_scatter(const void* ei){
  int idx = blockIdx.x*blockDim.x + threadIdx.x;
  if (idx >= N_EDGES*64) return;
  int e = idx >> 6, c = idx & 63;
  int r   = eidx(ei, e);
  int col = eidx(ei, N_EDGES + e);
  atomicAdd(&g_acc[col*64 + c], g_xwS[r*64 + c]);
}

__global__ void k_gcnT(const float* __restrict__ gb){
  int idx = blockIdx.x*blockDim.x + threadIdx.x;
  if (idx >= N_NODES*C_GCN) return;
  int n = idx >> 6, c = idx & 63;
  float v = rsqrtf(g_deg[n]) * (g_acc[idx] + g_xwS[idx]) + __ldg(&gb[c]);
  g_gcnT[c*N_NODES + n] = v;
}

__global__ void k_gpartT(const float* __restrict__ wih0, const float* __restrict__ bih0,
                         const float* __restrict__ bhh0){
  int n = blockIdx.x*blockDim.x + threadIdx.x;
  int g = blockIdx.y;            // original gate row 0..511
  if (n >= N_NODES) return;
  float s = __ldg(&bih0[g]) + __ldg(&bhh0[g]);
  #pragma unroll 8
  for (int j = 0; j < C_GCN; j++)
    s += g_gcnT[j*N_NODES + n] * __ldg(&wih0[g*96 + 32 + j]);
  g_gpart[(size_t)g*NPAD + n] = s;
}

// k-major, slot-grouped weight layout: W[k*512 + s*4 + g], g in {i,f,z,o}, row=g*128+s
__global__ void k_wcat(const float* wih0, const float* whh0, const float* wih1, const float* whh1,
                       const float* bih1, const float* bhh1){
  int idx = blockIdx.x*blockDim.x + threadIdx.x;
  if (idx < 256*G4){
    int k = idx / G4, c = idx - k*G4;
    int s = c >> 2, g = c & 3;
    int row = g*128 + s;
    g_W1[idx] = (k < H) ? whh1[row*H + k] : wih1[row*H + (k - H)];
  }
  if (idx < 160*G4){
    int k = idx / G4, c = idx - k*G4;
    int s = c >> 2, g = c & 3;
    int row = g*128 + s;
    g_W0[idx] = (k < H) ? whh0[row*H + k] : wih0[row*96 + (k - H)];
  }
  if (idx < G4) g_b1[idx] = bih1[idx] + bhh1[idx];
}

// ---------------- mega kernel helpers ----------------
__device__ __forceinline__ unsigned long long fma2(unsigned long long a, unsigned long long b,
                                                   unsigned long long c){
  unsigned long long d;
  asm("fma.rn.f32x2 %0, %1, %2, %3;" : "=l"(d) : "l"(a), "l"(b), "l"(c));
  return d;
}
__device__ __forceinline__ unsigned long long pk2(float a, float b){
  unsigned long long r;
  asm("mov.b64 %0, {%1, %2};" : "=l"(r) : "f"(a), "f"(b));
  return r;
}
__device__ __forceinline__ float sig_f(float x){
  return __fdividef(1.f, 1.f + __expf(-x));
}
__device__ __forceinline__ float tanh_f(float x){
  float ax = fminf(fabsf(x), 15.f);
  float e  = __expf(2.f*ax);
  float r  = 1.f - __fdividef(2.f, e + 1.f);
  return copysignf(r, x);
}

// acc[g][p] += sum_k A[k][m0+2p..] * W[k][s][g]
template<int ROWS>
__device__ __forceinline__ void accum_rows(const float* __restrict__ A,
                                           const float* __restrict__ W,
                                           int s4, int m0,
                                           unsigned long long acc[4][PAIRS]){
  #pragma unroll 4
  for (int k = 0; k < ROWS; k++){
    float4 a[9];
    const float4* ap = (const float4*)(A + k*MP + m0);
    #pragma unroll
    for (int i = 0; i < 9; i++) a[i] = ap[i];
    const unsigned long long* apq = (const unsigned long long*)a;
    float4 wv = __ldg((const float4*)(W + (size_t)k*G4 + s4));
    unsigned long long w;
    w = pk2(wv.x, wv.x);
    #pragma unroll
    for (int p = 0; p < PAIRS; p++) acc[0][p] = fma2(apq[p], w, acc[0][p]);
    w = pk2(wv.y, wv.y);
    #pragma unroll
    for (int p = 0; p < PAIRS; p++) acc[1][p] = fma2(apq[p], w, acc[1][p]);
    w = pk2(wv.z, wv.z);
    #pragma unroll
    for (int p = 0; p < PAIRS; p++) acc[2][p] = fma2(apq[p], w, acc[2][p]);
    w = pk2(wv.w, wv.w);
    #pragma unroll
    for (int p = 0; p < PAIRS; p++) acc[3][p] = fma2(apq[p], w, acc[3][p]);
  }
}

__device__ __forceinline__ void epilogue(unsigned long long acc[4][PAIRS],
                                         float* __restrict__ crow, float* __restrict__ hrow){
  #pragma unroll
  for (int p = 0; p < PAIRS; p++){
    float2 vi = *(float2*)&acc[0][p];
    float2 vf = *(float2*)&acc[1][p];
    float2 vz = *(float2*)&acc[2][p];
    float2 vo = *(float2*)&acc[3][p];
    float2 co = *(float2*)(crow + 2*p);
    float2 cn, hn;
    cn.x = sig_f(vf.x)*co.x + sig_f(vi.x)*tanh_f(vz.x);
    cn.y = sig_f(vf.y)*co.y + sig_f(vi.y)*tanh_f(vz.y);
    hn.x = sig_f(vo.x)*tanh_f(cn.x);
    hn.y = sig_f(vo.y)*tanh_f(cn.y);
    *(float2*)(crow + 2*p) = cn;
    *(float2*)(hrow + 2*p) = hn;
  }
}

// ---------------- mega kernel (fused 2-layer LSTM over T) ----------------
__global__ void __launch_bounds__(THREADS, 1)
k_mega(const float* __restrict__ seq, const float* __restrict__ fcw,
       const float* __restrict__ fcb, float* __restrict__ out){
  extern __shared__ float sm[];
  float* h0 = sm;                 // [128][72]
  float* h1 = sm + 128*MP;        // [128][72]
  float* sq = sm + 256*MP;        // [32][72]
  float* c0 = sm + 288*MP;        // [128][72]
  float* c1 = sm + 416*MP;        // [128][72]

  int tid  = threadIdx.x;
  int s    = tid >> 1;            // h slot 0..127
  int mt   = tid & 1;
  int m0   = mt * 36;
  int s4   = s * 4;
  int base = blockIdx.x * MP;

  for (int i = tid; i < 544*MP; i += THREADS) sm[i] = 0.f;
  __syncthreads();

  // stage sq for t=0
  for (int idx = tid; idx < S_SEQ*MP; idx += THREADS){
    int m = idx >> 5, i = idx & 31;
    int n = base + m; n = (n < N_NODES) ? n : (N_NODES - 1);
    sq[i*MP + m] = seq[(size_t)n*(T_SEQ*S_SEQ) + i];
  }
  __syncthreads();

  float* c0row = c0 + s*MP + m0;
  float* h0row = h0 + s*MP + m0;
  float* c1row = c1 + s*MP + m0;
  float* h1row = h1 + s*MP + m0;

  for (int t = 0; t < T_SEQ; t++){
    unsigned long long acc[4][PAIRS];

    // ---- layer 0: init from precomputed gcn-part + biases ----
    #pragma unroll
    for (int g = 0; g < 4; g++){
      const float* gp = g_gpart + (size_t)(g*128 + s)*NPAD + base + m0;
      #pragma unroll
      for (int p = 0; p < PAIRS; p++)
        acc[g][p] = *(const unsigned long long*)(gp + 2*p);
    }
    accum_rows<128>(h0, g_W0,           s4, m0, acc);
    accum_rows<32> (sq, g_W0 + 128*G4,  s4, m0, acc);
    __syncthreads();

    epilogue(acc, c0row, h0row);
    // stage sq for t+1 (gemm0 readers are past the sync; gemm1 never reads sq)
    if (t + 1 < T_SEQ){
      for (int idx = tid; idx < S_SEQ*MP; idx += THREADS){
        int m = idx >> 5, i = idx & 31;
        int n = base + m; n = (n < N_NODES) ? n : (N_NODES - 1);
        sq[i*MP + m] = seq[(size_t)n*(T_SEQ*S_SEQ) + (size_t)(t+1)*S_SEQ + i];
      }
    }
    __syncthreads();

    // ---- layer 1 ----
    #pragma unroll
    for (int g = 0; g < 4; g++){
      float b = __ldg(&g_b1[g*128 + s]);
      unsigned long long bb = pk2(b, b);
      #pragma unroll
      for (int p = 0; p < PAIRS; p++) acc[g][p] = bb;
    }
    accum_rows<128>(h1, g_W1,          s4, m0, acc);
    accum_rows<128>(h0, g_W1 + 128*G4, s4, m0, acc);
    __syncthreads();

    epilogue(acc, c1row, h1row);
    __syncthreads();
  }

  // ---- final FC on h1(T-1) ----
  float fb = __ldg(fcb);
  for (int m = tid; m < MP; m += THREADS){
    int n = base + m;
    if (n < N_NODES){
      float sum = fb;
      #pragma unroll 16
      for (int j = 0; j < H; j++) sum += h1[j*MP + m] * __ldg(&fcw[j]);
      out[n] = sum;
    }
  }
}

// ---------------- launch ----------------
extern "C" void kernel_launch(void* const* d_in, const int* in_sizes, int n_in,
                              void* d_out, int out_size){
  const float* seq  = (const float*)d_in[0];
  const void*  ei   = d_in[1];
  const float* nf   = (const float*)d_in[3];
  const float* gw   = (const float*)d_in[5];
  const float* gb   = (const float*)d_in[6];
  const float* wih0 = (const float*)d_in[7];
  const float* whh0 = (const float*)d_in[8];
  const float* bih0 = (const float*)d_in[9];
  const float* bhh0 = (const float*)d_in[10];
  const float* wih1 = (const float*)d_in[11];
  const float* whh1 = (const float*)d_in[12];
  const float* bih1 = (const float*)d_in[13];
  const float* bhh1 = (const float*)d_in[14];
  const float* fcw  = (const float*)d_in[15];
  const float* fcb  = (const float*)d_in[16];
  float* out = (float*)d_out;

  k_reset<<<1,1>>>();
  k_detect<<<64,256>>>((const int*)ei);
  k_init<<<(N_NODES*C_GCN + 255)/256, 256>>>();
  k_degedge<<<(N_EDGES + 255)/256, 256>>>(ei);
  k_xw<<<(N_NODES*C_GCN + 255)/256, 256>>>(nf, gw);
  k_scatter<<<(N_EDGES*64 + 255)/256, 256>>>(ei);
  k_gcnT<<<(N_NODES*C_GCN + 255)/256, 256>>>(gb);
  dim3 gp((N_NODES + 255)/256, G4);
  k_gpartT<<<gp, 256>>>(wih0, bih0, bhh0);
  k_wcat<<<(256*G4 + 255)/256, 256>>>(wih0, whh0, wih1, whh1, bih1, bhh1);

  size_t smem = (size_t)544*MP*sizeof(float);   // 156,672 B
  cudaFuncSetAttribute(k_mega, cudaFuncAttributeMaxDynamicSharedMemorySize, (int)smem);
  k_mega<<<NBLK, THREADS, smem>>>(seq, fcw, fcb, out);
}

// round 3
// speedup vs baseline: 1.8088x; 1.0030x over previous
#include <cuda_runtime.h>

#define N_NODES 10000
#define N_EDGES 160000
#define F_NODE  128
#define C_GCN   64
#define S_SEQ   32
#define T_SEQ   96
#define H       128
#define G4      512
#define MP      72
#define NBLK    148
#define NPAD    (NBLK*MP)     /* 10656 */
#define THREADS 256
#define PAIRS   18            /* 36 nodes per thread as f32x2 pairs */

// ---------------- scratch (zero-initialized device globals) ----------------
__device__ int   g_i32;                          // 1 => edge_index is int32
__device__ float g_deg [N_NODES];
__device__ float g_xwS [N_NODES*C_GCN];
__device__ float g_acc [N_NODES*C_GCN];
__device__ float g_gcnT[C_GCN*N_NODES];
__device__ float g_gpart[(size_t)G4*NPAD];       // pad region stays 0
__device__ float g_W0  [160*G4];                 // k-major [k][s][4]
__device__ float g_W1  [256*G4];
__device__ float g_b1  [G4];

__device__ __forceinline__ int eidx(const void* ei, int idx){
  if (g_i32) return ((const int*)ei)[idx];
  return (int)((const long long*)ei)[idx];
}

// ---------------- GCN + prep kernels ----------------
__global__ void k_reset(){ g_i32 = 0; }

__global__ void k_detect(const int* ei){
  int any = 0;
  for (int i = blockIdx.x*blockDim.x + threadIdx.x; i < N_EDGES; i += gridDim.x*blockDim.x)
    any |= ei[2*i+1];
  if (__syncthreads_or(any)) { if (threadIdx.x == 0) atomicOr(&g_i32, 1); }
}

__global__ void k_init(){
  int i = blockIdx.x*blockDim.x + threadIdx.x;
  if (i < N_NODES*C_GCN){
    g_acc[i] = 0.f;
    if (i < N_NODES) g_deg[i] = 1.f;   // self loop
  }
}

__global__ void k_degedge(const void* ei){
  int e = blockIdx.x*blockDim.x + threadIdx.x;
  if (e < N_EDGES) atomicAdd(&g_deg[eidx(ei, N_EDGES + e)], 1.f);
}

__global__ void k_xw(const float* __restrict__ nf, const float* __restrict__ gw){
  int idx = blockIdx.x*blockDim.x + threadIdx.x;
  if (idx >= N_NODES*C_GCN) return;
  int n = idx >> 6, c = idx & 63;
  float s = 0.f;
  #pragma unroll 8
  for (int k = 0; k < F_NODE; k++) s += nf[n*F_NODE + k] * __ldg(&gw[k*C_GCN + c]);
  g_xwS[idx] = s * rsqrtf(g_deg[n]);
}

__global__ void k_scatter(const void* ei){
  int idx = blockIdx.x*blockDim.x + threadIdx.x;
  if (idx >= N_EDGES*64) return;
  int e = idx >> 6, c = idx & 63;
  int r   = eidx(ei, e);
  int col = eidx(ei, N_EDGES + e);
  atomicAdd(&g_acc[col*64 + c], g_xwS[r*64 + c]);
}

__global__ void k_gcnT(const float* __restrict__ gb){
  int idx = blockIdx.x*blockDim.x + threadIdx.x;
  if (idx >= N_NODES*C_GCN) return;
  int n = idx >> 6, c = idx & 63;
  float v = rsqrtf(g_deg[n]) * (g_acc[idx] + g_xwS[idx]) + __ldg(&gb[c]);
  g_gcnT[c*N_NODES + n] = v;
}

__global__ void k_gpartT(const float* __restrict__ wih0, const float* __restrict__ bih0,
                         const float* __restrict__ bhh0){
  int n = blockIdx.x*blockDim.x + threadIdx.x;
  int g = blockIdx.y;            // original gate row 0..511
  if (n >= N_NODES) return;
  float s = __ldg(&bih0[g]) + __ldg(&bhh0[g]);
  #pragma unroll 8
  for (int j = 0; j < C_GCN; j++)
    s += g_gcnT[j*N_NODES + n] * __ldg(&wih0[g*96 + 32 + j]);
  g_gpart[(size_t)g*NPAD + n] = s;
}

// k-major, slot-grouped weight layout: W[k*512 + s*4 + g], g in {i,f,z,o}, row=g*128+s
__global__ void k_wcat(const float* wih0, const float* whh0, const float* wih1, const float* whh1,
                       const float* bih1, const float* bhh1){
  int idx = blockIdx.x*blockDim.x + threadIdx.x;
  if (idx < 256*G4){
    int k = idx / G4, c = idx - k*G4;
    int s = c >> 2, g = c & 3;
    int row = g*128 + s;
    g_W1[idx] = (k < H) ? whh1[row*H + k] : wih1[row*H + (k - H)];
  }
  if (idx < 160*G4){
    int k = idx / G4, c = idx - k*G4;
    int s = c >> 2, g = c & 3;
    int row = g*128 + s;
    g_W0[idx] = (k < H) ? whh0[row*H + k] : wih0[row*96 + (k - H)];
  }
  if (idx < G4) g_b1[idx] = bih1[idx] + bhh1[idx];
}

// ---------------- mega kernel helpers ----------------
__device__ __forceinline__ unsigned long long fma2(unsigned long long a, unsigned long long b,
                                                   unsigned long long c){
  unsigned long long d;
  asm("fma.rn.f32x2 %0, %1, %2, %3;" : "=l"(d) : "l"(a), "l"(b), "l"(c));
  return d;
}
__device__ __forceinline__ unsigned long long pk2(float a, float b){
  unsigned long long r;
  asm("mov.b64 %0, {%1, %2};" : "=l"(r) : "f"(a), "f"(b));
  return r;
}
__device__ __forceinline__ float sig_f(float x){
  return __fdividef(1.f, 1.f + __expf(-x));
}
__device__ __forceinline__ float tanh_f(float x){
  float ax = fminf(fabsf(x), 15.f);
  float e  = __expf(2.f*ax);
  float r  = 1.f - __fdividef(2.f, e + 1.f);
  return copysignf(r, x);
}

// acc[g][p] += sum_k A[k][m0+2p..] * W[k][s][g]
template<int ROWS>
__device__ __forceinline__ void accum_rows(const float* __restrict__ A,
                                           const float* __restrict__ W,
                                           int s4, int m0,
                                           unsigned long long acc[4][PAIRS]){
  #pragma unroll 4
  for (int k = 0; k < ROWS; k++){
    float4 a[9];
    const float4* ap = (const float4*)(A + k*MP + m0);
    #pragma unroll
    for (int i = 0; i < 9; i++) a[i] = ap[i];
    const unsigned long long* apq = (const unsigned long long*)a;
    float4 wv = __ldg((const float4*)(W + (size_t)k*G4 + s4));
    unsigned long long w;
    w = pk2(wv.x, wv.x);
    #pragma unroll
    for (int p = 0; p < PAIRS; p++) acc[0][p] = fma2(apq[p], w, acc[0][p]);
    w = pk2(wv.y, wv.y);
    #pragma unroll
    for (int p = 0; p < PAIRS; p++) acc[1][p] = fma2(apq[p], w, acc[1][p]);
    w = pk2(wv.z, wv.z);
    #pragma unroll
    for (int p = 0; p < PAIRS; p++) acc[2][p] = fma2(apq[p], w, acc[2][p]);
    w = pk2(wv.w, wv.w);
    #pragma unroll
    for (int p = 0; p < PAIRS; p++) acc[3][p] = fma2(apq[p], w, acc[3][p]);
  }
}

__device__ __forceinline__ void epilogue(unsigned long long acc[4][PAIRS],
                                         float* __restrict__ crow, float* __restrict__ hrow){
  #pragma unroll
  for (int p = 0; p < PAIRS; p++){
    float2 vi = *(float2*)&acc[0][p];
    float2 vf = *(float2*)&acc[1][p];
    float2 vz = *(float2*)&acc[2][p];
    float2 vo = *(float2*)&acc[3][p];
    float2 co = *(float2*)(crow + 2*p);
    float2 cn, hn;
    cn.x = sig_f(vf.x)*co.x + sig_f(vi.x)*tanh_f(vz.x);
    cn.y = sig_f(vf.y)*co.y + sig_f(vi.y)*tanh_f(vz.y);
    hn.x = sig_f(vo.x)*tanh_f(cn.x);
    hn.y = sig_f(vo.y)*tanh_f(cn.y);
    *(float2*)(crow + 2*p) = cn;
    *(float2*)(hrow + 2*p) = hn;
  }
}

// ---------------- mega kernel (fused 2-layer LSTM over T) ----------------
__global__ void __launch_bounds__(THREADS, 1)
k_mega(const float* __restrict__ seq, const float* __restrict__ fcw,
       const float* __restrict__ fcb, float* __restrict__ out){
  extern __shared__ float sm[];
  float* h0 = sm;                 // [128][72]
  float* h1 = sm + 128*MP;        // [128][72]
  float* sq = sm + 256*MP;        // [32][72]
  float* c0 = sm + 288*MP;        // [128][72]
  float* c1 = sm + 416*MP;        // [128][72]

  int tid  = threadIdx.x;
  int s    = tid >> 1;            // h slot 0..127
  int mt   = tid & 1;
  int m0   = mt * 36;
  int s4   = s * 4;
  int base = blockIdx.x * MP;

  for (int i = tid; i < 544*MP; i += THREADS) sm[i] = 0.f;
  __syncthreads();

  // stage sq for t=0
  for (int idx = tid; idx < S_SEQ*MP; idx += THREADS){
    int m = idx >> 5, i = idx & 31;
    int n = base + m; n = (n < N_NODES) ? n : (N_NODES - 1);
    sq[i*MP + m] = seq[(size_t)n*(T_SEQ*S_SEQ) + i];
  }
  __syncthreads();

  float* c0row = c0 + s*MP + m0;
  float* h0row = h0 + s*MP + m0;
  float* c1row = c1 + s*MP + m0;
  float* h1row = h1 + s*MP + m0;

  for (int t = 0; t < T_SEQ; t++){
    unsigned long long acc[4][PAIRS];

    // ---- layer 0: init from precomputed gcn-part + biases ----
    #pragma unroll
    for (int g = 0; g < 4; g++){
      const float* gp = g_gpart + (size_t)(g*128 + s)*NPAD + base + m0;
      #pragma unroll
      for (int p = 0; p < PAIRS; p++)
        acc[g][p] = *(const unsigned long long*)(gp + 2*p);
    }
    accum_rows<128>(h0, g_W0,           s4, m0, acc);
    accum_rows<32> (sq, g_W0 + 128*G4,  s4, m0, acc);
    __syncthreads();

    epilogue(acc, c0row, h0row);
    // stage sq for t+1 (gemm0 readers are past the sync; gemm1 never reads sq)
    if (t + 1 < T_SEQ){
      for (int idx = tid; idx < S_SEQ*MP; idx += THREADS){
        int m = idx >> 5, i = idx & 31;
        int n = base + m; n = (n < N_NODES) ? n : (N_NODES - 1);
        sq[i*MP + m] = seq[(size_t)n*(T_SEQ*S_SEQ) + (size_t)(t+1)*S_SEQ + i];
      }
    }
    __syncthreads();

    // ---- layer 1 ----
    #pragma unroll
    for (int g = 0; g < 4; g++){
      float b = __ldg(&g_b1[g*128 + s]);
      unsigned long long bb = pk2(b, b);
      #pragma unroll
      for (int p = 0; p < PAIRS; p++) acc[g][p] = bb;
    }
    accum_rows<128>(h1, g_W1,          s4, m0, acc);
    accum_rows<128>(h0, g_W1 + 128*G4, s4, m0, acc);
    __syncthreads();

    epilogue(acc, c1row, h1row);
    __syncthreads();
  }

  // ---- final FC on h1(T-1) ----
  float fb = __ldg(fcb);
  for (int m = tid; m < MP; m += THREADS){
    int n = base + m;
    if (n < N_NODES){
      float sum = fb;
      #pragma unroll 16
      for (int j = 0; j < H; j++) sum += h1[j*MP + m] * __ldg(&fcw[j]);
      out[n] = sum;
    }
  }
}

// ---------------- launch ----------------
extern "C" void kernel_launch(void* const* d_in, const int* in_sizes, int n_in,
                              void* d_out, int out_size){
  const float* seq  = (const float*)d_in[0];
  const void*  ei   = d_in[1];
  const float* nf   = (const float*)d_in[3];
  const float* gw   = (const float*)d_in[5];
  const float* gb   = (const float*)d_in[6];
  const float* wih0 = (const float*)d_in[7];
  const float* whh0 = (const float*)d_in[8];
  const float* bih0 = (const float*)d_in[9];
  const float* bhh0 = (const float*)d_in[10];
  const float* wih1 = (const float*)d_in[11];
  const float* whh1 = (const float*)d_in[12];
  const float* bih1 = (const float*)d_in[13];
  const float* bhh1 = (const float*)d_in[14];
  const float* fcw  = (const float*)d_in[15];
  const float* fcb  = (const float*)d_in[16];
  float* out = (float*)d_out;

  k_reset<<<1,1>>>();
  k_detect<<<64,256>>>((const int*)ei);
  k_init<<<(N_NODES*C_GCN + 255)/256, 256>>>();
  k_degedge<<<(N_EDGES + 255)/256, 256>>>(ei);
  k_xw<<<(N_NODES*C_GCN + 255)/256, 256>>>(nf, gw);
  k_scatter<<<(N_EDGES*64 + 255)/256, 256>>>(ei);
  k_gcnT<<<(N_NODES*C_GCN + 255)/256, 256>>>(gb);
  dim3 gp((N_NODES + 255)/256, G4);
  k_gpartT<<<gp, 256>>>(wih0, bih0, bhh0);
  k_wcat<<<(256*G4 + 255)/256, 256>>>(wih0, whh0, wih1, whh1, bih1, bhh1);

  size_t smem = (size_t)544*MP*sizeof(float);   // 156,672 B
  cudaFuncSetAttribute(k_mega, cudaFuncAttributeMaxDynamicSharedMemorySize, (int)smem);
  k_mega<<<NBLK, THREADS, smem>>>(seq, fcw, fcb, out);
}

// round 5
// speedup vs baseline: 3.8275x; 2.1161x over previous
#include <cuda_runtime.h>
#include <cuda_bf16.h>
#include <cstdint>

#define N_NODES 10000
#define N_EDGES 160000
#define F_NODE  128
#define C_GCN   64
#define S_SEQ   32
#define T_SEQ   96
#define H       128
#define NP      72
#define NBLK    148
#define NPAD    (NBLK*NP)      /* 10656 */
#define THREADS 256

#define XF_U    10368          /* 18 kslots x 9 ntiles x 32 lanes x 2 u32 */
#define SM_U    (2*XF_U + 2*9216)
#define SMEM_B  (SM_U*4)       /* 156672 B */

// ---------------- device globals ----------------
__device__ int    g_i32;
__device__ float  g_deg [N_NODES];
__device__ float  g_xwS [N_NODES*C_GCN];
__device__ float  g_acc [N_NODES*C_GCN];
__device__ float  g_gcnT[C_GCN*N_NODES];
__device__ float4 g_gpF [NBLK*8*4*9*32];   // [blk][w][g][nt][lane] d-frag f32x4
__device__ uint4  g_WF  [53248];           // A-frags: layer0 20480, layer1 32768

__device__ __forceinline__ int eidx(const void* ei, int idx){
  if (g_i32) return ((const int*)ei)[idx];
  return (int)((const long long*)ei)[idx];
}

// ---------------- GCN prep ----------------
__global__ void k_reset(){ g_i32 = 0; }

__global__ void k_detect(const int* ei){
  int any = 0;
  for (int i = blockIdx.x*blockDim.x + threadIdx.x; i < N_EDGES; i += gridDim.x*blockDim.x)
    any |= ei[2*i+1];
  if (__syncthreads_or(any)) { if (threadIdx.x == 0) atomicOr(&g_i32, 1); }
}

__global__ void k_init(){
  int i = blockIdx.x*blockDim.x + threadIdx.x;
  if (i < N_NODES*C_GCN){
    g_acc[i] = 0.f;
    if (i < N_NODES) g_deg[i] = 1.f;
  }
}

__global__ void k_degedge(const void* ei){
  int e = blockIdx.x*blockDim.x + threadIdx.x;
  if (e < N_EDGES) atomicAdd(&g_deg[eidx(ei, N_EDGES + e)], 1.f);
}

__global__ void k_xw(const float* __restrict__ nf, const float* __restrict__ gw){
  int idx = blockIdx.x*blockDim.x + threadIdx.x;
  if (idx >= N_NODES*C_GCN) return;
  int n = idx >> 6, c = idx & 63;
  float s = 0.f;
  #pragma unroll 8
  for (int k = 0; k < F_NODE; k++) s += nf[n*F_NODE + k] * __ldg(&gw[k*C_GCN + c]);
  g_xwS[idx] = s * rsqrtf(g_deg[n]);
}

__global__ void k_scatter(const void* ei){
  int idx = blockIdx.x*blockDim.x + threadIdx.x;
  if (idx >= N_EDGES*64) return;
  int e = idx >> 6, c = idx & 63;
  atomicAdd(&g_acc[eidx(ei, N_EDGES + e)*64 + c], g_xwS[eidx(ei, e)*64 + c]);
}

__global__ void k_gcnT(const float* __restrict__ gb){
  int idx = blockIdx.x*blockDim.x + threadIdx.x;
  if (idx >= N_NODES*C_GCN) return;
  int n = idx >> 6, c = idx & 63;
  float v = rsqrtf(g_deg[n]) * (g_acc[idx] + g_xwS[idx]) + __ldg(&gb[c]);
  g_gcnT[c*N_NODES + n] = v;
}

// gpart (gcn + both layer-0 biases) baked into D-fragment layout
__global__ void k_gpf(const float* __restrict__ wih0, const float* __restrict__ bih0,
                      const float* __restrict__ bhh0){
  int idx = blockIdx.x*blockDim.x + threadIdx.x;
  if (idx >= 512*NPAD) return;
  int m = idx / NPAD, p = idx - m*NPAD;
  int blk = p / NP, pl = p - blk*NP;
  int a = p; if (a >= N_NODES) a = N_NODES - 1;
  float s = __ldg(&bih0[m]) + __ldg(&bhh0[m]);
  #pragma unroll 8
  for (int j = 0; j < 64; j++)
    s += g_gcnT[j*N_NODES + a] * __ldg(&wih0[m*96 + 32 + j]);
  int g = m >> 7, ml = m & 127, w = ml >> 4, t8 = ml & 15, T = t8 & 7, hf = t8 >> 3;
  int nt = pl >> 3, n8 = pl & 7, cq = n8 >> 1, dn = n8 & 1;
  int lane = T*4 + cq, r = hf*2 + dn;
  ((float*)g_gpF)[((((blk*8 + w)*4 + g)*9 + nt)*32 + lane)*4 + r] = s;
}

__device__ __forceinline__ unsigned short bfbits(float v){
  __nv_bfloat16 b = __float2bfloat16(v);
  return *(unsigned short*)&b;
}
__device__ __forceinline__ float bf2f(unsigned short u){
  return __bfloat162float(*(__nv_bfloat16*)&u);
}

// Weights pre-permuted into mma A-fragment order (hi/lo split).
__global__ void k_wf(const float* __restrict__ wih0, const float* __restrict__ whh0,
                     const float* __restrict__ wih1, const float* __restrict__ whh1){
  int idx = blockIdx.x*blockDim.x + threadIdx.x;
  if (idx >= 212992) return;
  int reg = idx & 3, l = (idx >> 2) & 31;
  int w = (idx >> 7) & 7, g = (idx >> 10) & 3, prec = (idx >> 12) & 1, k16 = idx >> 13;
  int layer = (k16 >= 10);
  int k16l = layer ? k16 - 10 : k16;
  int T = l >> 2, cq = l & 3;
  int row  = T + 8*(reg & 1);
  int colb = 2*cq + 8*(reg >> 1);
  int m = g*128 + w*16 + row;
  int k = k16l*16 + colb;                 // k even; pair never straddles 128
  float v0, v1;
  if (layer){
    if (k < 128){ v0 = whh1[m*128 + k];      v1 = whh1[m*128 + k + 1]; }
    else        { v0 = wih1[m*128 + k - 128]; v1 = wih1[m*128 + k - 127]; }
  } else {
    if (k < 128){ v0 = whh0[m*128 + k];      v1 = whh0[m*128 + k + 1]; }
    else        { v0 = wih0[m*96 + k - 128];  v1 = wih0[m*96 + k - 127]; }
  }
  unsigned short b0, b1;
  if (prec == 0){ b0 = bfbits(v0); b1 = bfbits(v1); }
  else {
    b0 = bfbits(v0 - bf2f(bfbits(v0)));
    b1 = bfbits(v1 - bf2f(bfbits(v1)));
  }
  ((uint32_t*)g_WF)[idx] = ((uint32_t)b1 << 16) | (uint32_t)b0;
}

// ---------------- mega kernel ----------------
__device__ __forceinline__ float sig_f(float x){ return __fdividef(1.f, 1.f + __expf(-x)); }
__device__ __forceinline__ float tanh_f(float x){
  float ax = fminf(fabsf(x), 15.f);
  float r = 1.f - __fdividef(2.f, __expf(2.f*ax) + 1.f);
  return copysignf(r, x);
}

__device__ __forceinline__ void mma_bf16(float* d, const uint32_t* a, uint2 b){
  asm volatile("mma.sync.aligned.m16n8k16.row.col.f32.bf16.bf16.f32 "
               "{%0,%1,%2,%3}, {%4,%5,%6,%7}, {%8,%9}, {%0,%1,%2,%3};"
               : "+f"(d[0]), "+f"(d[1]), "+f"(d[2]), "+f"(d[3])
               : "r"(a[0]), "r"(a[1]), "r"(a[2]), "r"(a[3]), "r"(b.x), "r"(b.y));
}

template<int LAYER>
__device__ __forceinline__ void gemm_layer(const uint32_t* __restrict__ XH,
                                           const uint32_t* __restrict__ XL,
                                           float acc[36][4], int w, int l){
  const uint4* WF = g_WF + (LAYER ? 20480 : 0);
  const int NK = LAYER ? 16 : 10;
  #pragma unroll 1
  for (int k16 = 0; k16 < NK; k16++){
    int ks = LAYER ? k16 : 8 + k16;      // layer0 B slots 8..17, layer1 0..15
    uint4 ahi[4], alo[4];
    #pragma unroll
    for (int g = 0; g < 4; g++){
      int i4 = k16*2048 + g*256 + w*32 + l;
      ahi[g] = __ldg(&WF[i4]);
      alo[g] = __ldg(&WF[i4 + 1024]);
    }
    #pragma unroll
    for (int nt = 0; nt < 9; nt++){
      uint2 bh = *(const uint2*)&XH[((ks*9 + nt)*32 + l)*2];
      uint2 bl = *(const uint2*)&XL[((ks*9 + nt)*32 + l)*2];
      #pragma unroll
      for (int g = 0; g < 4; g++){
        mma_bf16(acc[g*9+nt], (const uint32_t*)&ahi[g], bh);
        mma_bf16(acc[g*9+nt], (const uint32_t*)&ahi[g], bl);
        mma_bf16(acc[g*9+nt], (const uint32_t*)&alo[g], bh);
      }
    }
  }
}

__device__ __forceinline__ void epilogue(float acc[36][4], float* csm,
                                         uint32_t* XH, uint32_t* XL,
                                         int w, int l, int ksbase){
  int T = l >> 2, cq = l & 3;
  int ks = ksbase + w;
  #pragma unroll
  for (int nt = 0; nt < 9; nt++){
    #pragma unroll
    for (int r = 0; r < 4; r++){
      int half = r >> 1, dn = r & 1;
      int s = w*16 + T + 8*half;
      int n = nt*8 + 2*cq + dn;
      float gi = acc[nt][r], gf = acc[9+nt][r], gz = acc[18+nt][r], go = acc[27+nt][r];
      float cold = csm[s*NP + n];
      float cn = sig_f(gf)*cold + sig_f(gi)*tanh_f(gz);
      csm[s*NP + n] = cn;
      float h = sig_f(go)*tanh_f(cn);
      unsigned short hb = bfbits(h);
      unsigned short lb = bfbits(h - bf2f(hb));
      int lane = ((n & 7) << 2) + (T >> 1);
      int ui = ((ks*9 + nt)*32 + lane)*2 + half;
      ((unsigned short*)&XH[ui])[T & 1] = hb;
      ((unsigned short*)&XL[ui])[T & 1] = lb;
    }
  }
}

__device__ __forceinline__ void stage_seq(const float* __restrict__ seq, int base, int t,
                                          uint32_t* XH, uint32_t* XL, int tid){
  for (int idx = tid; idx < NP*S_SEQ; idx += THREADS){
    int nl = idx >> 5, i = idx & 31;
    int a = base + nl; if (a >= N_NODES) a = N_NODES - 1;
    float v = seq[(size_t)a*(T_SEQ*S_SEQ) + t*S_SEQ + i];
    unsigned short hb = bfbits(v);
    unsigned short lb = bfbits(v - bf2f(hb));
    int ks = 16 + (i >> 4), kl = i & 15;
    int r = kl >> 3, cq = (kl & 7) >> 1, hf = kl & 1;
    int lane = ((nl & 7) << 2) + cq;
    int nt = nl >> 3;
    int ui = ((ks*9 + nt)*32 + lane)*2 + r;
    ((unsigned short*)&XH[ui])[hf] = hb;
    ((unsigned short*)&XL[ui])[hf] = lb;
  }
}

__global__ void __launch_bounds__(THREADS, 1)
k_mega(const float* __restrict__ seq, const float* __restrict__ bih1,
       const float* __restrict__ bhh1, const float* __restrict__ fcw,
       const float* __restrict__ fcb, float* __restrict__ out){
  extern __shared__ uint32_t smu[];
  uint32_t* XH = smu;
  uint32_t* XL = smu + XF_U;
  float* c0 = (float*)(smu + 2*XF_U);
  float* c1 = c0 + 9216;
  int tid = threadIdx.x, w = tid >> 5, l = tid & 31;
  int blk = blockIdx.x, base = blk*NP;
  int T = l >> 2;

  for (int i = tid; i < SM_U; i += THREADS) smu[i] = 0;
  __syncthreads();
  stage_seq(seq, base, 0, XH, XL, tid);

  float b1v[4][2];
  #pragma unroll
  for (int g = 0; g < 4; g++)
    #pragma unroll
    for (int hf = 0; hf < 2; hf++){
      int m = g*128 + w*16 + T + 8*hf;
      b1v[g][hf] = __ldg(&bih1[m]) + __ldg(&bhh1[m]);
    }
  __syncthreads();

  const float4* gp = g_gpF + (blk*8 + w)*1152;

  for (int t = 0; t < T_SEQ; t++){
    float acc[36][4];
    #pragma unroll
    for (int g = 0; g < 4; g++)
      #pragma unroll
      for (int nt = 0; nt < 9; nt++){
        float4 v = __ldg(&gp[g*288 + nt*32 + l]);
        acc[g*9+nt][0] = v.x; acc[g*9+nt][1] = v.y;
        acc[g*9+nt][2] = v.z; acc[g*9+nt][3] = v.w;
      }
    gemm_layer<0>(XH, XL, acc, w, l);
    __syncthreads();
    epilogue(acc, c0, XH, XL, w, l, 8);
    if (t + 1 < T_SEQ) stage_seq(seq, base, t + 1, XH, XL, tid);
    __syncthreads();

    #pragma unroll
    for (int g = 0; g < 4; g++)
      #pragma unroll
      for (int nt = 0; nt < 9; nt++){
        acc[g*9+nt][0] = b1v[g][0]; acc[g*9+nt][1] = b1v[g][0];
        acc[g*9+nt][2] = b1v[g][1]; acc[g*9+nt][3] = b1v[g][1];
      }
    gemm_layer<1>(XH, XL, acc, w, l);
    __syncthreads();
    epilogue(acc, c1, XH, XL, w, l, 0);
    __syncthreads();
  }

  if (tid < NP){
    int a = base + tid;
    if (a < N_NODES){
      float sum = __ldg(fcb);
      int nt = tid >> 3, lanebase = (tid & 7) << 2;
      #pragma unroll 8
      for (int s = 0; s < H; s++){
        int ks = s >> 4, kl = s & 15, r = kl >> 3, cq = (kl & 7) >> 1, hf = kl & 1;
        int ui = ((ks*9 + nt)*32 + lanebase + cq)*2 + r;
        unsigned short hb = ((unsigned short*)&XH[ui])[hf];
        unsigned short lb = ((unsigned short*)&XL[ui])[hf];
        sum += (bf2f(hb) + bf2f(lb)) * __ldg(&fcw[s]);
      }
      out[a] = sum;
    }
  }
}

// ---------------- launch ----------------
extern "C" void kernel_launch(void* const* d_in, const int* in_sizes, int n_in,
                              void* d_out, int out_size){
  const float* seq  = (const float*)d_in[0];
  const void*  ei   = d_in[1];
  const float* nf   = (const float*)d_in[3];
  const float* gw   = (const float*)d_in[5];
  const float* gb   = (const float*)d_in[6];
  const float* wih0 = (const float*)d_in[7];
  const float* whh0 = (const float*)d_in[8];
  const float* bih0 = (const float*)d_in[9];
  const float* bhh0 = (const float*)d_in[10];
  const float* wih1 = (const float*)d_in[11];
  const float* whh1 = (const float*)d_in[12];
  const float* bih1 = (const float*)d_in[13];
  const float* bhh1 = (const float*)d_in[14];
  const float* fcw  = (const float*)d_in[15];
  const float* fcb  = (const float*)d_in[16];
  float* out = (float*)d_out;

  k_reset<<<1,1>>>();
  k_detect<<<64,256>>>((const int*)ei);
  k_init<<<(N_NODES*C_GCN + 255)/256, 256>>>();
  k_degedge<<<(N_EDGES + 255)/256, 256>>>(ei);
  k_xw<<<(N_NODES*C_GCN + 255)/256, 256>>>(nf, gw);
  k_scatter<<<(N_EDGES*64 + 255)/256, 256>>>(ei);
  k_gcnT<<<(N_NODES*C_GCN + 255)/256, 256>>>(gb);
  k_gpf<<<(512*NPAD + 255)/256, 256>>>(wih0, bih0, bhh0);
  k_wf<<<(212992 + 255)/256, 256>>>(wih0, whh0, wih1, whh1);

  cudaFuncSetAttribute(k_mega, cudaFuncAttributeMaxDynamicSharedMemorySize, SMEM_B);
  k_mega<<<NBLK, THREADS, SMEM_B>>>(seq, bih1, bhh1, fcw, fcb, out);
}

// round 6
// speedup vs baseline: 4.8320x; 1.2624x over previous
#include <cuda_runtime.h>
#include <cuda_fp16.h>
#include <cstdint>

#define N_NODES 10000
#define N_EDGES 160000
#define F_NODE  128
#define C_GCN   64
#define S_SEQ   32
#define T_SEQ   96
#define H       128
#define NP      72
#define NBLK    148
#define NPAD    (NBLK*NP)      /* 10656 */
#define THREADS 256

#define XF_U    10368          /* 18 kslots x 9 ntiles x 32 lanes x 2 u32 */
#define SM_U    (2*XF_U + 2*9216)
#define SMEM_B  (SM_U*4)       /* 156672 B */

// ---------------- device globals ----------------
__device__ int    g_i32;
__device__ float  g_deg [N_NODES];
__device__ float  g_xwS [N_NODES*C_GCN];
__device__ float  g_acc [N_NODES*C_GCN];
__device__ float  g_gcnT[C_GCN*N_NODES];
__device__ float4 g_gpF [NBLK*8*4*9*32];   // [blk][w][g][nt][lane] d-frag f32x4
__device__ uint4  g_WF  [26624];           // fp16 A-frags: layer0 10240, layer1 16384

__device__ __forceinline__ int eidx(const void* ei, int idx){
  if (g_i32) return ((const int*)ei)[idx];
  return (int)((const long long*)ei)[idx];
}

// ---------------- GCN prep ----------------
__global__ void k_reset(){ g_i32 = 0; }

__global__ void k_detect(const int* ei){
  int any = 0;
  for (int i = blockIdx.x*blockDim.x + threadIdx.x; i < N_EDGES; i += gridDim.x*blockDim.x)
    any |= ei[2*i+1];
  if (__syncthreads_or(any)) { if (threadIdx.x == 0) atomicOr(&g_i32, 1); }
}

__global__ void k_init(){
  int i = blockIdx.x*blockDim.x + threadIdx.x;
  if (i < N_NODES*C_GCN){
    g_acc[i] = 0.f;
    if (i < N_NODES) g_deg[i] = 1.f;
  }
}

__global__ void k_degedge(const void* ei){
  int e = blockIdx.x*blockDim.x + threadIdx.x;
  if (e < N_EDGES) atomicAdd(&g_deg[eidx(ei, N_EDGES + e)], 1.f);
}

__global__ void k_xw(const float* __restrict__ nf, const float* __restrict__ gw){
  int idx = blockIdx.x*blockDim.x + threadIdx.x;
  if (idx >= N_NODES*C_GCN) return;
  int n = idx >> 6, c = idx & 63;
  float s = 0.f;
  #pragma unroll 8
  for (int k = 0; k < F_NODE; k++) s += nf[n*F_NODE + k] * __ldg(&gw[k*C_GCN + c]);
  g_xwS[idx] = s * rsqrtf(g_deg[n]);
}

__global__ void k_scatter(const void* ei){
  int idx = blockIdx.x*blockDim.x + threadIdx.x;
  if (idx >= N_EDGES*64) return;
  int e = idx >> 6, c = idx & 63;
  atomicAdd(&g_acc[eidx(ei, N_EDGES + e)*64 + c], g_xwS[eidx(ei, e)*64 + c]);
}

__global__ void k_gcnT(const float* __restrict__ gb){
  int idx = blockIdx.x*blockDim.x + threadIdx.x;
  if (idx >= N_NODES*C_GCN) return;
  int n = idx >> 6, c = idx & 63;
  float v = rsqrtf(g_deg[n]) * (g_acc[idx] + g_xwS[idx]) + __ldg(&gb[c]);
  g_gcnT[c*N_NODES + n] = v;
}

// gpart (gcn + both layer-0 biases) baked into D-fragment layout
__global__ void k_gpf(const float* __restrict__ wih0, const float* __restrict__ bih0,
                      const float* __restrict__ bhh0){
  int idx = blockIdx.x*blockDim.x + threadIdx.x;
  if (idx >= 512*NPAD) return;
  int m = idx / NPAD, p = idx - m*NPAD;
  int blk = p / NP, pl = p - blk*NP;
  int a = p; if (a >= N_NODES) a = N_NODES - 1;
  float s = __ldg(&bih0[m]) + __ldg(&bhh0[m]);
  #pragma unroll 8
  for (int j = 0; j < 64; j++)
    s += g_gcnT[j*N_NODES + a] * __ldg(&wih0[m*96 + 32 + j]);
  int g = m >> 7, ml = m & 127, w = ml >> 4, t8 = ml & 15, T = t8 & 7, hf = t8 >> 3;
  int nt = pl >> 3, n8 = pl & 7, cq = n8 >> 1, dn = n8 & 1;
  int lane = T*4 + cq, r = hf*2 + dn;
  ((float*)g_gpF)[((((blk*8 + w)*4 + g)*9 + nt)*32 + lane)*4 + r] = s;
}

__device__ __forceinline__ unsigned short hfbits(float v){
  __half h = __float2half_rn(v);
  return *(unsigned short*)&h;
}
__device__ __forceinline__ float hf2f(unsigned short u){
  return __half2float(*(__half*)&u);
}

// Weights pre-permuted into mma A-fragment order, single fp16.
// idx = [k16][g][w][lane][reg]; layer = (k16 >= 10)
__global__ void k_wf(const float* __restrict__ wih0, const float* __restrict__ whh0,
                     const float* __restrict__ wih1, const float* __restrict__ whh1){
  int idx = blockIdx.x*blockDim.x + threadIdx.x;
  if (idx >= 106496) return;
  int reg = idx & 3, l = (idx >> 2) & 31;
  int w = (idx >> 7) & 7, g = (idx >> 10) & 3, k16 = idx >> 12;
  int layer = (k16 >= 10);
  int k16l = layer ? k16 - 10 : k16;
  int T = l >> 2, cq = l & 3;
  int row  = T + 8*(reg & 1);
  int colb = 2*cq + 8*(reg >> 1);
  int m = g*128 + w*16 + row;
  int k = k16l*16 + colb;                 // k even; pair never straddles 128
  float v0, v1;
  if (layer){
    if (k < 128){ v0 = whh1[m*128 + k];       v1 = whh1[m*128 + k + 1]; }
    else        { v0 = wih1[m*128 + k - 128]; v1 = wih1[m*128 + k - 127]; }
  } else {
    if (k < 128){ v0 = whh0[m*128 + k];       v1 = whh0[m*128 + k + 1]; }
    else        { v0 = wih0[m*96 + k - 128];  v1 = wih0[m*96 + k - 127]; }
  }
  ((uint32_t*)g_WF)[idx] = ((uint32_t)hfbits(v1) << 16) | (uint32_t)hfbits(v0);
}

// ---------------- mega kernel ----------------
__device__ __forceinline__ float sig_f(float x){ return __fdividef(1.f, 1.f + __expf(-x)); }
__device__ __forceinline__ float tanh_f(float x){
  float ax = fminf(fabsf(x), 15.f);
  float r = 1.f - __fdividef(2.f, __expf(2.f*ax) + 1.f);
  return copysignf(r, x);
}

__device__ __forceinline__ void mma_f16(float* d, const uint32_t* a, uint2 b){
  asm volatile("mma.sync.aligned.m16n8k16.row.col.f32.f16.f16.f32 "
               "{%0,%1,%2,%3}, {%4,%5,%6,%7}, {%8,%9}, {%0,%1,%2,%3};"
               : "+f"(d[0]), "+f"(d[1]), "+f"(d[2]), "+f"(d[3])
               : "r"(a[0]), "r"(a[1]), "r"(a[2]), "r"(a[3]), "r"(b.x), "r"(b.y));
}

template<int LAYER>
__device__ __forceinline__ void gemm_layer(const uint32_t* __restrict__ XH,
                                           const uint32_t* __restrict__ XL,
                                           float acc[36][4], int w, int l){
  const uint4* WF = g_WF + (LAYER ? 10240 : 0);
  const int NK = LAYER ? 16 : 10;
  uint4 a_cur[4], a_nxt[4];
  #pragma unroll
  for (int g = 0; g < 4; g++) a_cur[g] = __ldg(&WF[g*256 + w*32 + l]);
  #pragma unroll 1
  for (int k16 = 0; k16 < NK; k16++){
    int ks = LAYER ? k16 : 8 + k16;      // layer0 B slots 8..17, layer1 0..15
    if (k16 + 1 < NK){
      #pragma unroll
      for (int g = 0; g < 4; g++)
        a_nxt[g] = __ldg(&WF[(k16+1)*1024 + g*256 + w*32 + l]);
    }
    #pragma unroll
    for (int nt = 0; nt < 9; nt++){
      uint2 bh = *(const uint2*)&XH[((ks*9 + nt)*32 + l)*2];
      uint2 bl = *(const uint2*)&XL[((ks*9 + nt)*32 + l)*2];
      #pragma unroll
      for (int g = 0; g < 4; g++){
        mma_f16(acc[g*9+nt], (const uint32_t*)&a_cur[g], bh);
        mma_f16(acc[g*9+nt], (const uint32_t*)&a_cur[g], bl);
      }
    }
    #pragma unroll
    for (int g = 0; g < 4; g++) a_cur[g] = a_nxt[g];
  }
}

__device__ __forceinline__ void epilogue(float acc[36][4], float* csm,
                                         uint32_t* XH, uint32_t* XL,
                                         int w, int l, int ksbase){
  int T = l >> 2, cq = l & 3;
  int ks = ksbase + w;
  #pragma unroll
  for (int nt = 0; nt < 9; nt++){
    #pragma unroll
    for (int r = 0; r < 4; r++){
      int half = r >> 1, dn = r & 1;
      int s = w*16 + T + 8*half;
      int n = nt*8 + 2*cq + dn;
      float gi = acc[nt][r], gf = acc[9+nt][r], gz = acc[18+nt][r], go = acc[27+nt][r];
      float cold = csm[s*NP + n];
      float cn = sig_f(gf)*cold + sig_f(gi)*tanh_f(gz);
      csm[s*NP + n] = cn;
      float h = sig_f(go)*tanh_f(cn);
      unsigned short hb = hfbits(h);
      unsigned short lb = hfbits(h - hf2f(hb));
      int lane = ((n & 7) << 2) + (T >> 1);
      int ui = ((ks*9 + nt)*32 + lane)*2 + half;
      ((unsigned short*)&XH[ui])[T & 1] = hb;
      ((unsigned short*)&XL[ui])[T & 1] = lb;
    }
  }
}

__device__ __forceinline__ void stage_seq(const float* __restrict__ seq, int base, int t,
                                          uint32_t* XH, uint32_t* XL, int tid){
  for (int idx = tid; idx < NP*S_SEQ; idx += THREADS){
    int nl = idx >> 5, i = idx & 31;
    int a = base + nl; if (a >= N_NODES) a = N_NODES - 1;
    float v = seq[(size_t)a*(T_SEQ*S_SEQ) + t*S_SEQ + i];
    unsigned short hb = hfbits(v);
    unsigned short lb = hfbits(v - hf2f(hb));
    int ks = 16 + (i >> 4), kl = i & 15;
    int r = kl >> 3, cq = (kl & 7) >> 1, hf = kl & 1;
    int lane = ((nl & 7) << 2) + cq;
    int nt = nl >> 3;
    int ui = ((ks*9 + nt)*32 + lane)*2 + r;
    ((unsigned short*)&XH[ui])[hf] = hb;
    ((unsigned short*)&XL[ui])[hf] = lb;
  }
}

__global__ void __launch_bounds__(THREADS, 1)
k_mega(const float* __restrict__ seq, const float* __restrict__ bih1,
       const float* __restrict__ bhh1, const float* __restrict__ fcw,
       const float* __restrict__ fcb, float* __restrict__ out){
  extern __shared__ uint32_t smu[];
  uint32_t* XH = smu;
  uint32_t* XL = smu + XF_U;
  float* c0 = (float*)(smu + 2*XF_U);
  float* c1 = c0 + 9216;
  int tid = threadIdx.x, w = tid >> 5, l = tid & 31;
  int blk = blockIdx.x, base = blk*NP;
  int T = l >> 2;

  for (int i = tid; i < SM_U; i += THREADS) smu[i] = 0;
  __syncthreads();
  stage_seq(seq, base, 0, XH, XL, tid);

  float b1v[4][2];
  #pragma unroll
  for (int g = 0; g < 4; g++)
    #pragma unroll
    for (int hf = 0; hf < 2; hf++){
      int m = g*128 + w*16 + T + 8*hf;
      b1v[g][hf] = __ldg(&bih1[m]) + __ldg(&bhh1[m]);
    }
  __syncthreads();

  const float4* gp = g_gpF + (blk*8 + w)*1152;

  for (int t = 0; t < T_SEQ; t++){
    float acc[36][4];
    #pragma unroll
    for (int g = 0; g < 4; g++)
      #pragma unroll
      for (int nt = 0; nt < 9; nt++){
        float4 v = __ldg(&gp[g*288 + nt*32 + l]);
        acc[g*9+nt][0] = v.x; acc[g*9+nt][1] = v.y;
        acc[g*9+nt][2] = v.z; acc[g*9+nt][3] = v.w;
      }
    gemm_layer<0>(XH, XL, acc, w, l);
    __syncthreads();
    epilogue(acc, c0, XH, XL, w, l, 8);
    if (t + 1 < T_SEQ) stage_seq(seq, base, t + 1, XH, XL, tid);
    __syncthreads();

    #pragma unroll
    for (int g = 0; g < 4; g++)
      #pragma unroll
      for (int nt = 0; nt < 9; nt++){
        acc[g*9+nt][0] = b1v[g][0]; acc[g*9+nt][1] = b1v[g][0];
        acc[g*9+nt][2] = b1v[g][1]; acc[g*9+nt][3] = b1v[g][1];
      }
    gemm_layer<1>(XH, XL, acc, w, l);
    __syncthreads();
    epilogue(acc, c1, XH, XL, w, l, 0);
    // no sync needed here: h1 slots (0..7) are not read until after two later syncs
  }
  __syncthreads();

  if (tid < NP){
    int a = base + tid;
    if (a < N_NODES){
      float sum = __ldg(fcb);
      int nt = tid >> 3, lanebase = (tid & 7) << 2;
      #pragma unroll 8
      for (int s = 0; s < H; s++){
        int ks = s >> 4, kl = s & 15, r = kl >> 3, cq = (kl & 7) >> 1, hf = kl & 1;
        int ui = ((ks*9 + nt)*32 + lanebase + cq)*2 + r;
        unsigned short hb = ((unsigned short*)&XH[ui])[hf];
        unsigned short lb = ((unsigned short*)&XL[ui])[hf];
        sum += (hf2f(hb) + hf2f(lb)) * __ldg(&fcw[s]);
      }
      out[a] = sum;
    }
  }
}

// ---------------- launch ----------------
extern "C" void kernel_launch(void* const* d_in, const int* in_sizes, int n_in,
                              void* d_out, int out_size){
  const float* seq  = (const float*)d_in[0];
  const void*  ei   = d_in[1];
  const float* nf   = (const float*)d_in[3];
  const float* gw   = (const float*)d_in[5];
  const float* gb   = (const float*)d_in[6];
  const float* wih0 = (const float*)d_in[7];
  const float* whh0 = (const float*)d_in[8];
  const float* bih0 = (const float*)d_in[9];
  const float* bhh0 = (const float*)d_in[10];
  const float* wih1 = (const float*)d_in[11];
  const float* whh1 = (const float*)d_in[12];
  const float* bih1 = (const float*)d_in[13];
  const float* bhh1 = (const float*)d_in[14];
  const float* fcw  = (const float*)d_in[15];
  const float* fcb  = (const float*)d_in[16];
  float* out = (float*)d_out;

  k_reset<<<1,1>>>();
  k_detect<<<64,256>>>((const int*)ei);
  k_init<<<(N_NODES*C_GCN + 255)/256, 256>>>();
  k_degedge<<<(N_EDGES + 255)/256, 256>>>(ei);
  k_xw<<<(N_NODES*C_GCN + 255)/256, 256>>>(nf, gw);
  k_scatter<<<(N_EDGES*64 + 255)/256, 256>>>(ei);
  k_gcnT<<<(N_NODES*C_GCN + 255)/256, 256>>>(gb);
  k_gpf<<<(512*NPAD + 255)/256, 256>>>(wih0, bih0, bhh0);
  k_wf<<<(106496 + 255)/256, 256>>>(wih0, whh0, wih1, whh1);

  cudaFuncSetAttribute(k_mega, cudaFuncAttributeMaxDynamicSharedMemorySize, SMEM_B);
  k_mega<<<NBLK, THREADS, SMEM_B>>>(seq, bih1, bhh1, fcw, fcb, out);
}

// round 7
// speedup vs baseline: 7.6152x; 1.5760x over previous
#include <cuda_runtime.h>
#include <cuda_fp16.h>
#include <cstdint>

#define N_NODES 10000
#define N_EDGES 160000
#define F_NODE  128
#define C_GCN   64
#define S_SEQ   32
#define T_SEQ   96
#define H       128
#define NP      72
#define NBLK    148
#define NPAD    (NBLK*NP)      /* 10656 */
#define THREADS 256

#define XF_U    10368          /* 18 kslots x 9 ntiles x 32 lanes x 2 u32 */
#define SM_U    (XF_U + 2*9216)
#define SMEM_B  (SM_U*4)

// ---------------- device globals ----------------
__device__ int    g_i32;
__device__ float  g_deg [N_NODES];
__device__ float  g_xwS [N_NODES*C_GCN];
__device__ float  g_acc [N_NODES*C_GCN];
__device__ float  g_gcnT[C_GCN*N_NODES];
__device__ float4 g_gpF [NBLK*8*4*9*32];   // [blk][w][g][nt][lane] d-frag f32x4
__device__ uint4  g_WF  [26624];           // fp16 A-frags: layer0 10240, layer1 16384

__device__ __forceinline__ int eidx(const void* ei, int idx){
  if (g_i32) return ((const int*)ei)[idx];
  return (int)((const long long*)ei)[idx];
}

// ---------------- GCN prep ----------------
__global__ void k_reset(){ g_i32 = 0; }

__global__ void k_detect(const int* ei){
  int any = 0;
  for (int i = blockIdx.x*blockDim.x + threadIdx.x; i < N_EDGES; i += gridDim.x*blockDim.x)
    any |= ei[2*i+1];
  if (__syncthreads_or(any)) { if (threadIdx.x == 0) atomicOr(&g_i32, 1); }
}

__global__ void k_init(){
  int i = blockIdx.x*blockDim.x + threadIdx.x;
  if (i < N_NODES*C_GCN){
    g_acc[i] = 0.f;
    if (i < N_NODES) g_deg[i] = 1.f;
  }
}

__global__ void k_degedge(const void* ei){
  int e = blockIdx.x*blockDim.x + threadIdx.x;
  if (e < N_EDGES) atomicAdd(&g_deg[eidx(ei, N_EDGES + e)], 1.f);
}

__global__ void k_xw(const float* __restrict__ nf, const float* __restrict__ gw){
  int idx = blockIdx.x*blockDim.x + threadIdx.x;
  if (idx >= N_NODES*C_GCN) return;
  int n = idx >> 6, c = idx & 63;
  float s = 0.f;
  #pragma unroll 8
  for (int k = 0; k < F_NODE; k++) s += nf[n*F_NODE + k] * __ldg(&gw[k*C_GCN + c]);
  g_xwS[idx] = s * rsqrtf(g_deg[n]);
}

__global__ void k_scatter(const void* ei){
  int idx = blockIdx.x*blockDim.x + threadIdx.x;
  if (idx >= N_EDGES*64) return;
  int e = idx >> 6, c = idx & 63;
  atomicAdd(&g_acc[eidx(ei, N_EDGES + e)*64 + c], g_xwS[eidx(ei, e)*64 + c]);
}

__global__ void k_gcnT(const float* __restrict__ gb){
  int idx = blockIdx.x*blockDim.x + threadIdx.x;
  if (idx >= N_NODES*C_GCN) return;
  int n = idx >> 6, c = idx & 63;
  float v = rsqrtf(g_deg[n]) * (g_acc[idx] + g_xwS[idx]) + __ldg(&gb[c]);
  g_gcnT[c*N_NODES + n] = v;
}

// gpart (gcn + both layer-0 biases) baked into D-fragment layout
__global__ void k_gpf(const float* __restrict__ wih0, const float* __restrict__ bih0,
                      const float* __restrict__ bhh0){
  int idx = blockIdx.x*blockDim.x + threadIdx.x;
  if (idx >= 512*NPAD) return;
  int m = idx / NPAD, p = idx - m*NPAD;
  int blk = p / NP, pl = p - blk*NP;
  int a = p; if (a >= N_NODES) a = N_NODES - 1;
  float s = __ldg(&bih0[m]) + __ldg(&bhh0[m]);
  #pragma unroll 8
  for (int j = 0; j < 64; j++)
    s += g_gcnT[j*N_NODES + a] * __ldg(&wih0[m*96 + 32 + j]);
  int g = m >> 7, ml = m & 127, w = ml >> 4, t8 = ml & 15, T = t8 & 7, hf = t8 >> 3;
  int nt = pl >> 3, n8 = pl & 7, cq = n8 >> 1, dn = n8 & 1;
  int lane = T*4 + cq, r = hf*2 + dn;
  ((float*)g_gpF)[((((blk*8 + w)*4 + g)*9 + nt)*32 + lane)*4 + r] = s;
}

__device__ __forceinline__ unsigned short hfbits(float v){
  __half h = __float2half_rn(v);
  return *(unsigned short*)&h;
}
__device__ __forceinline__ float hf2f(unsigned short u){
  return __half2float(*(__half*)&u);
}

// Weights pre-permuted into mma A-fragment order, single fp16.
// idx = [k16][g][w][lane][reg]; layer = (k16 >= 10)
__global__ void k_wf(const float* __restrict__ wih0, const float* __restrict__ whh0,
                     const float* __restrict__ wih1, const float* __restrict__ whh1){
  int idx = blockIdx.x*blockDim.x + threadIdx.x;
  if (idx >= 106496) return;
  int reg = idx & 3, l = (idx >> 2) & 31;
  int w = (idx >> 7) & 7, g = (idx >> 10) & 3, k16 = idx >> 12;
  int layer = (k16 >= 10);
  int k16l = layer ? k16 - 10 : k16;
  int T = l >> 2, cq = l & 3;
  int row  = T + 8*(reg & 1);
  int colb = 2*cq + 8*(reg >> 1);
  int m = g*128 + w*16 + row;
  int k = k16l*16 + colb;                 // k even; pair never straddles 128
  float v0, v1;
  if (layer){
    if (k < 128){ v0 = whh1[m*128 + k];       v1 = whh1[m*128 + k + 1]; }
    else        { v0 = wih1[m*128 + k - 128]; v1 = wih1[m*128 + k - 127]; }
  } else {
    if (k < 128){ v0 = whh0[m*128 + k];       v1 = whh0[m*128 + k + 1]; }
    else        { v0 = wih0[m*96 + k - 128];  v1 = wih0[m*96 + k - 127]; }
  }
  ((uint32_t*)g_WF)[idx] = ((uint32_t)hfbits(v1) << 16) | (uint32_t)hfbits(v0);
}

// ---------------- mega kernel ----------------
__device__ __forceinline__ float tanh_a(float x){
  float r; asm("tanh.approx.f32 %0, %1;" : "=f"(r) : "f"(x)); return r;
}
__device__ __forceinline__ float sig_a(float x){
  return fmaf(0.5f, tanh_a(0.5f*x), 0.5f);
}

__device__ __forceinline__ void mma_f16(float* d, const uint32_t* a, uint2 b){
  asm volatile("mma.sync.aligned.m16n8k16.row.col.f32.f16.f16.f32 "
               "{%0,%1,%2,%3}, {%4,%5,%6,%7}, {%8,%9}, {%0,%1,%2,%3};"
               : "+f"(d[0]), "+f"(d[1]), "+f"(d[2]), "+f"(d[3])
               : "r"(a[0]), "r"(a[1]), "r"(a[2]), "r"(a[3]), "r"(b.x), "r"(b.y));
}

template<int LAYER>
__device__ __forceinline__ void gemm_layer(const uint32_t* __restrict__ XH,
                                           float acc[36][4], int w, int l){
  const uint4* WF = g_WF + (LAYER ? 10240 : 0);
  const int NK = LAYER ? 16 : 10;
  uint4 a_cur[4], a_nxt[4];
  #pragma unroll
  for (int g = 0; g < 4; g++) a_cur[g] = __ldg(&WF[g*256 + w*32 + l]);
  #pragma unroll 1
  for (int k16 = 0; k16 < NK; k16++){
    int ks = LAYER ? k16 : 8 + k16;      // layer0 B slots 8..17, layer1 0..15
    if (k16 + 1 < NK){
      #pragma unroll
      for (int g = 0; g < 4; g++)
        a_nxt[g] = __ldg(&WF[(k16+1)*1024 + g*256 + w*32 + l]);
    }
    #pragma unroll
    for (int nt = 0; nt < 9; nt++){
      uint2 bh = *(const uint2*)&XH[((ks*9 + nt)*32 + l)*2];
      #pragma unroll
      for (int g = 0; g < 4; g++)
        mma_f16(acc[g*9+nt], (const uint32_t*)&a_cur[g], bh);
    }
    #pragma unroll
    for (int g = 0; g < 4; g++) a_cur[g] = a_nxt[g];
  }
}

__device__ __forceinline__ void epilogue(float acc[36][4], float* csm,
                                         uint32_t* XH, int w, int l, int ksbase){
  int T = l >> 2, cq = l & 3;
  int ks = ksbase + w;
  #pragma unroll
  for (int nt = 0; nt < 9; nt++){
    #pragma unroll
    for (int r = 0; r < 4; r++){
      int half = r >> 1, dn = r & 1;
      int s = w*16 + T + 8*half;
      int n = nt*8 + 2*cq + dn;
      float gi = acc[nt][r], gf = acc[9+nt][r], gz = acc[18+nt][r], go = acc[27+nt][r];
      float cold = csm[s*NP + n];
      float cn = sig_a(gf)*cold + sig_a(gi)*tanh_a(gz);
      csm[s*NP + n] = cn;
      float h = sig_a(go)*tanh_a(cn);
      int lane = ((n & 7) << 2) + (T >> 1);
      int ui = ((ks*9 + nt)*32 + lane)*2 + half;
      ((unsigned short*)&XH[ui])[T & 1] = hfbits(h);
    }
  }
}

__device__ __forceinline__ void stage_seq(const float* __restrict__ seq, int base, int t,
                                          uint32_t* XH, int tid){
  for (int idx = tid; idx < NP*S_SEQ; idx += THREADS){
    int nl = idx >> 5, i = idx & 31;
    int a = base + nl; if (a >= N_NODES) a = N_NODES - 1;
    float v = seq[(size_t)a*(T_SEQ*S_SEQ) + t*S_SEQ + i];
    int ks = 16 + (i >> 4), kl = i & 15;
    int r = kl >> 3, cq = (kl & 7) >> 1, hf = kl & 1;
    int lane = ((nl & 7) << 2) + cq;
    int nt = nl >> 3;
    int ui = ((ks*9 + nt)*32 + lane)*2 + r;
    ((unsigned short*)&XH[ui])[hf] = hfbits(v);
  }
}

__global__ void __launch_bounds__(THREADS, 1)
k_mega(const float* __restrict__ seq, const float* __restrict__ bih1,
       const float* __restrict__ bhh1, const float* __restrict__ fcw,
       const float* __restrict__ fcb, float* __restrict__ out){
  extern __shared__ uint32_t smu[];
  uint32_t* XH = smu;
  float* c0 = (float*)(smu + XF_U);
  float* c1 = c0 + 9216;
  int tid = threadIdx.x, w = tid >> 5, l = tid & 31;
  int blk = blockIdx.x, base = blk*NP;
  int T = l >> 2;

  for (int i = tid; i < SM_U; i += THREADS) smu[i] = 0;
  __syncthreads();
  stage_seq(seq, base, 0, XH, tid);

  float b1v[4][2];
  #pragma unroll
  for (int g = 0; g < 4; g++)
    #pragma unroll
    for (int hf = 0; hf < 2; hf++){
      int m = g*128 + w*16 + T + 8*hf;
      b1v[g][hf] = __ldg(&bih1[m]) + __ldg(&bhh1[m]);
    }
  __syncthreads();

  const float4* gp = g_gpF + (blk*8 + w)*1152;

  for (int t = 0; t < T_SEQ; t++){
    float acc[36][4];
    #pragma unroll
    for (int g = 0; g < 4; g++)
      #pragma unroll
      for (int nt = 0; nt < 9; nt++){
        float4 v = __ldg(&gp[g*288 + nt*32 + l]);
        acc[g*9+nt][0] = v.x; acc[g*9+nt][1] = v.y;
        acc[g*9+nt][2] = v.z; acc[g*9+nt][3] = v.w;
      }
    gemm_layer<0>(XH, acc, w, l);
    __syncthreads();
    epilogue(acc, c0, XH, w, l, 8);
    if (t + 1 < T_SEQ) stage_seq(seq, base, t + 1, XH, tid);
    __syncthreads();

    #pragma unroll
    for (int g = 0; g < 4; g++)
      #pragma unroll
      for (int nt = 0; nt < 9; nt++){
        acc[g*9+nt][0] = b1v[g][0]; acc[g*9+nt][1] = b1v[g][0];
        acc[g*9+nt][2] = b1v[g][1]; acc[g*9+nt][3] = b1v[g][1];
      }
    gemm_layer<1>(XH, acc, w, l);
    __syncthreads();
    epilogue(acc, c1, XH, w, l, 0);
    // no sync needed: h1 slots (0..7) are not read until after two later syncs
  }
  __syncthreads();

  if (tid < NP){
    int a = base + tid;
    if (a < N_NODES){
      float sum = __ldg(fcb);
      int nt = tid >> 3, lanebase = (tid & 7) << 2;
      #pragma unroll 8
      for (int s = 0; s < H; s++){
        int ks = s >> 4, kl = s & 15, r = kl >> 3, cq = (kl & 7) >> 1, hf = kl & 1;
        int ui = ((ks*9 + nt)*32 + lanebase + cq)*2 + r;
        sum += hf2f(((unsigned short*)&XH[ui])[hf]) * __ldg(&fcw[s]);
      }
      out[a] = sum;
    }
  }
}

// ---------------- launch ----------------
extern "C" void kernel_launch(void* const* d_in, const int* in_sizes, int n_in,
                              void* d_out, int out_size){
  const float* seq  = (const float*)d_in[0];
  const void*  ei   = d_in[1];
  const float* nf   = (const float*)d_in[3];
  const float* gw   = (const float*)d_in[5];
  const float* gb   = (const float*)d_in[6];
  const float* wih0 = (const float*)d_in[7];
  const float* whh0 = (const float*)d_in[8];
  const float* bih0 = (const float*)d_in[9];
  const float* bhh0 = (const float*)d_in[10];
  const float* wih1 = (const float*)d_in[11];
  const float* whh1 = (const float*)d_in[12];
  const float* bih1 = (const float*)d_in[13];
  const float* bhh1 = (const float*)d_in[14];
  const float* fcw  = (const float*)d_in[15];
  const float* fcb  = (const float*)d_in[16];
  float* out = (float*)d_out;

  k_reset<<<1,1>>>();
  k_detect<<<64,256>>>((const int*)ei);
  k_init<<<(N_NODES*C_GCN + 255)/256, 256>>>();
  k_degedge<<<(N_EDGES + 255)/256, 256>>>(ei);
  k_xw<<<(N_NODES*C_GCN + 255)/256, 256>>>(nf, gw);
  k_scatter<<<(N_EDGES*64 + 255)/256, 256>>>(ei);
  k_gcnT<<<(N_NODES*C_GCN + 255)/256, 256>>>(gb);
  k_gpf<<<(512*NPAD + 255)/256, 256>>>(wih0, bih0, bhh0);
  k_wf<<<(106496 + 255)/256, 256>>>(wih0, whh0, wih1, whh1);

  cudaFuncSetAttribute(k_mega, cudaFuncAttributeMaxDynamicSharedMemorySize, SMEM_B);
  k_mega<<<NBLK, THREADS, SMEM_B>>>(seq, bih1, bhh1, fcw, fcb, out);
}

// round 8
// speedup vs baseline: 7.8072x; 1.0252x over previous
#include <cuda_runtime.h>
#include <cuda_fp16.h>
#include <cstdint>

#define N_NODES 10000
#define N_EDGES 160000
#define F_NODE  128
#define C_GCN   64
#define S_SEQ   32
#define T_SEQ   96
#define H       128
#define NP      72
#define NBLK    148
#define NPAD    (NBLK*NP)      /* 10656 */
#define THREADS 256

#define XF_U    10368          /* 18 kslots x 9 ntiles x 32 lanes x 2 u32 */
#define ZERO_U  (XF_U + 2*9216)          /* XH + c0 + c1 = 28800 u32 */
#define W0S_U4  7168                     /* 7 k16 chunks cached in smem */
#define SMEM_B  ((ZERO_U + W0S_U4*4)*4)  /* 229888 B */

// ---------------- device globals ----------------
__device__ int    g_i32;
__device__ float  g_deg [N_NODES];
__device__ float  g_xwS [N_NODES*C_GCN];
__device__ float  g_acc [N_NODES*C_GCN];
__device__ float  g_gcnT[C_GCN*N_NODES];
__device__ float4 g_gpF [NBLK*8*4*9*32];   // [blk][w][g][nt][lane] d-frag f32x4
__device__ uint4  g_WF  [26624];           // fp16 A-frags: layer0 10240, layer1 16384

__device__ __forceinline__ int eidx(const void* ei, int idx){
  if (g_i32) return ((const int*)ei)[idx];
  return (int)((const long long*)ei)[idx];
}

// ---------------- GCN prep ----------------
__global__ void k_reset(){ g_i32 = 0; }

__global__ void k_detect(const int* ei){
  int any = 0;
  for (int i = blockIdx.x*blockDim.x + threadIdx.x; i < N_EDGES; i += gridDim.x*blockDim.x)
    any |= ei[2*i+1];
  if (__syncthreads_or(any)) { if (threadIdx.x == 0) atomicOr(&g_i32, 1); }
}

__global__ void k_init(){
  int i = blockIdx.x*blockDim.x + threadIdx.x;
  if (i < N_NODES*C_GCN){
    g_acc[i] = 0.f;
    if (i < N_NODES) g_deg[i] = 1.f;
  }
}

__global__ void k_degedge(const void* ei){
  int e = blockIdx.x*blockDim.x + threadIdx.x;
  if (e < N_EDGES) atomicAdd(&g_deg[eidx(ei, N_EDGES + e)], 1.f);
}

__global__ void k_xw(const float* __restrict__ nf, const float* __restrict__ gw){
  int idx = blockIdx.x*blockDim.x + threadIdx.x;
  if (idx >= N_NODES*C_GCN) return;
  int n = idx >> 6, c = idx & 63;
  float s = 0.f;
  #pragma unroll 8
  for (int k = 0; k < F_NODE; k++) s += nf[n*F_NODE + k] * __ldg(&gw[k*C_GCN + c]);
  g_xwS[idx] = s * rsqrtf(g_deg[n]);
}

__global__ void k_scatter(const void* ei){
  int idx = blockIdx.x*blockDim.x + threadIdx.x;
  if (idx >= N_EDGES*64) return;
  int e = idx >> 6, c = idx & 63;
  atomicAdd(&g_acc[eidx(ei, N_EDGES + e)*64 + c], g_xwS[eidx(ei, e)*64 + c]);
}

__global__ void k_gcnT(const float* __restrict__ gb){
  int idx = blockIdx.x*blockDim.x + threadIdx.x;
  if (idx >= N_NODES*C_GCN) return;
  int n = idx >> 6, c = idx & 63;
  float v = rsqrtf(g_deg[n]) * (g_acc[idx] + g_xwS[idx]) + __ldg(&gb[c]);
  g_gcnT[c*N_NODES + n] = v;
}

// gpart (gcn + both layer-0 biases) baked into D-fragment layout
__global__ void k_gpf(const float* __restrict__ wih0, const float* __restrict__ bih0,
                      const float* __restrict__ bhh0){
  int idx = blockIdx.x*blockDim.x + threadIdx.x;
  if (idx >= 512*NPAD) return;
  int m = idx / NPAD, p = idx - m*NPAD;
  int blk = p / NP, pl = p - blk*NP;
  int a = p; if (a >= N_NODES) a = N_NODES - 1;
  float s = __ldg(&bih0[m]) + __ldg(&bhh0[m]);
  #pragma unroll 8
  for (int j = 0; j < 64; j++)
    s += g_gcnT[j*N_NODES + a] * __ldg(&wih0[m*96 + 32 + j]);
  int g = m >> 7, ml = m & 127, w = ml >> 4, t8 = ml & 15, T = t8 & 7, hf = t8 >> 3;
  int nt = pl >> 3, n8 = pl & 7, cq = n8 >> 1, dn = n8 & 1;
  int lane = T*4 + cq, r = hf*2 + dn;
  ((float*)g_gpF)[((((blk*8 + w)*4 + g)*9 + nt)*32 + lane)*4 + r] = s;
}

__device__ __forceinline__ unsigned short hfbits(float v){
  __half h = __float2half_rn(v);
  return *(unsigned short*)&h;
}
__device__ __forceinline__ float hf2f(unsigned short u){
  return __half2float(*(__half*)&u);
}

// Weights pre-permuted into mma A-fragment order, single fp16.
// idx = [k16][g][w][lane][reg]; layer = (k16 >= 10)
__global__ void k_wf(const float* __restrict__ wih0, const float* __restrict__ whh0,
                     const float* __restrict__ wih1, const float* __restrict__ whh1){
  int idx = blockIdx.x*blockDim.x + threadIdx.x;
  if (idx >= 106496) return;
  int reg = idx & 3, l = (idx >> 2) & 31;
  int w = (idx >> 7) & 7, g = (idx >> 10) & 3, k16 = idx >> 12;
  int layer = (k16 >= 10);
  int k16l = layer ? k16 - 10 : k16;
  int T = l >> 2, cq = l & 3;
  int row  = T + 8*(reg & 1);
  int colb = 2*cq + 8*(reg >> 1);
  int m = g*128 + w*16 + row;
  int k = k16l*16 + colb;                 // k even; pair never straddles 128
  float v0, v1;
  if (layer){
    if (k < 128){ v0 = whh1[m*128 + k];       v1 = whh1[m*128 + k + 1]; }
    else        { v0 = wih1[m*128 + k - 128]; v1 = wih1[m*128 + k - 127]; }
  } else {
    if (k < 128){ v0 = whh0[m*128 + k];       v1 = whh0[m*128 + k + 1]; }
    else        { v0 = wih0[m*96 + k - 128];  v1 = wih0[m*96 + k - 127]; }
  }
  ((uint32_t*)g_WF)[idx] = ((uint32_t)hfbits(v1) << 16) | (uint32_t)hfbits(v0);
}

// ---------------- mega kernel ----------------
__device__ __forceinline__ float tanh_a(float x){
  float r; asm("tanh.approx.f32 %0, %1;" : "=f"(r) : "f"(x)); return r;
}
__device__ __forceinline__ float sig_a(float x){
  return fmaf(0.5f, tanh_a(0.5f*x), 0.5f);
}

__device__ __forceinline__ void mma_f16(float* d, const uint32_t* a, uint2 b){
  asm volatile("mma.sync.aligned.m16n8k16.row.col.f32.f16.f16.f32 "
               "{%0,%1,%2,%3}, {%4,%5,%6,%7}, {%8,%9}, {%0,%1,%2,%3};"
               : "+f"(d[0]), "+f"(d[1]), "+f"(d[2]), "+f"(d[3])
               : "r"(a[0]), "r"(a[1]), "r"(a[2]), "r"(a[3]), "r"(b.x), "r"(b.y));
}

// layer 0: k16 0..6 from smem cache, 7..9 streamed from L2 (prefetched up front)
__device__ __forceinline__ void gemm_l0(const uint32_t* __restrict__ XH,
                                        const uint4* __restrict__ W0S,
                                        float acc[36][4], int o, int l){
  uint4 s7[4], s8[4], s9[4];
  #pragma unroll
  for (int g = 0; g < 4; g++) s7[g] = __ldg(&g_WF[7*1024 + g*256 + o]);
  #pragma unroll
  for (int g = 0; g < 4; g++) s8[g] = __ldg(&g_WF[8*1024 + g*256 + o]);
  #pragma unroll 1
  for (int k16 = 0; k16 < 7; k16++){
    int ks = 8 + k16;
    uint4 a_cur[4];
    #pragma unroll
    for (int g = 0; g < 4; g++) a_cur[g] = W0S[k16*1024 + g*256 + o];
    if (k16 == 0){
      #pragma unroll
      for (int g = 0; g < 4; g++) s9[g] = __ldg(&g_WF[9*1024 + g*256 + o]);
    }
    #pragma unroll
    for (int nt = 0; nt < 9; nt++){
      uint2 bh = *(const uint2*)&XH[((ks*9 + nt)*32 + l)*2];
      #pragma unroll
      for (int g = 0; g < 4; g++)
        mma_f16(acc[g*9+nt], (const uint32_t*)&a_cur[g], bh);
    }
  }
  #pragma unroll
  for (int nt = 0; nt < 9; nt++){
    uint2 bh = *(const uint2*)&XH[((15*9 + nt)*32 + l)*2];
    #pragma unroll
    for (int g = 0; g < 4; g++) mma_f16(acc[g*9+nt], (const uint32_t*)&s7[g], bh);
  }
  #pragma unroll
  for (int nt = 0; nt < 9; nt++){
    uint2 bh = *(const uint2*)&XH[((16*9 + nt)*32 + l)*2];
    #pragma unroll
    for (int g = 0; g < 4; g++) mma_f16(acc[g*9+nt], (const uint32_t*)&s8[g], bh);
  }
  #pragma unroll
  for (int nt = 0; nt < 9; nt++){
    uint2 bh = *(const uint2*)&XH[((17*9 + nt)*32 + l)*2];
    #pragma unroll
    for (int g = 0; g < 4; g++) mma_f16(acc[g*9+nt], (const uint32_t*)&s9[g], bh);
  }
}

// layer 1: all 16 k16 streamed, first frag preloaded by caller (hidden under epi0)
__device__ __forceinline__ void gemm_l1(const uint32_t* __restrict__ XH,
                                        float acc[36][4], int o, int l,
                                        const uint4 a0[4]){
  const uint4* WF = g_WF + 10240;
  uint4 a_cur[4] = {a0[0], a0[1], a0[2], a0[3]};
  #pragma unroll 1
  for (int k16 = 0; k16 < 16; k16++){
    uint4 a_nxt[4];
    if (k16 < 15){
      #pragma unroll
      for (int g = 0; g < 4; g++) a_nxt[g] = __ldg(&WF[(k16+1)*1024 + g*256 + o]);
    }
    #pragma unroll
    for (int nt = 0; nt < 9; nt++){
      uint2 bh = *(const uint2*)&XH[((k16*9 + nt)*32 + l)*2];
      #pragma unroll
      for (int g = 0; g < 4; g++)
        mma_f16(acc[g*9+nt], (const uint32_t*)&a_cur[g], bh);
    }
    #pragma unroll
    for (int g = 0; g < 4; g++) a_cur[g] = a_nxt[g];
  }
}

__device__ __forceinline__ void epilogue(float acc[36][4], float* csm,
                                         uint32_t* XH, int w, int l, int ksbase){
  int T = l >> 2, cq = l & 3;
  int ks = ksbase + w;
  int s_lo = w*16 + T, s_hi = s_lo + 8;
  #pragma unroll
  for (int nt = 0; nt < 9; nt++){
    int n0 = nt*8 + 2*cq;
    float2 cl = *(float2*)&csm[s_lo*NP + n0];
    float2 ch = *(float2*)&csm[s_hi*NP + n0];
    float cold[4] = {cl.x, cl.y, ch.x, ch.y};
    float2 nl, nh;
    #pragma unroll
    for (int r = 0; r < 4; r++){
      int half = r >> 1;
      float gi = acc[nt][r], gf = acc[9+nt][r], gz = acc[18+nt][r], go = acc[27+nt][r];
      float cn = sig_a(gf)*cold[r] + sig_a(gi)*tanh_a(gz);
      if (r == 0) nl.x = cn; else if (r == 1) nl.y = cn;
      else if (r == 2) nh.x = cn; else nh.y = cn;
      float h = sig_a(go)*tanh_a(cn);
      int n = n0 + (r & 1);
      int lane = ((n & 7) << 2) + (T >> 1);
      int ui = ((ks*9 + nt)*32 + lane)*2 + half;
      ((unsigned short*)&XH[ui])[T & 1] = hfbits(h);
    }
    *(float2*)&csm[s_lo*NP + n0] = nl;
    *(float2*)&csm[s_hi*NP + n0] = nh;
  }
}

__device__ __forceinline__ void stage_seq(const float* __restrict__ seq, int base, int t,
                                          uint32_t* XH, int tid){
  for (int idx = tid; idx < NP*S_SEQ; idx += THREADS){
    int nl = idx >> 5, i = idx & 31;
    int a = base + nl; if (a >= N_NODES) a = N_NODES - 1;
    float v = seq[(size_t)a*(T_SEQ*S_SEQ) + t*S_SEQ + i];
    int ks = 16 + (i >> 4), kl = i & 15;
    int r = kl >> 3, cq = (kl & 7) >> 1, hf = kl & 1;
    int lane = ((nl & 7) << 2) + cq;
    int nt = nl >> 3;
    int ui = ((ks*9 + nt)*32 + lane)*2 + r;
    ((unsigned short*)&XH[ui])[hf] = hfbits(v);
  }
}

__global__ void __launch_bounds__(THREADS)
k_mega(const float* __restrict__ seq, const float* __restrict__ bih1,
       const float* __restrict__ bhh1, const float* __restrict__ fcw,
       const float* __restrict__ fcb, float* __restrict__ out){
  extern __shared__ uint32_t smu[];
  uint32_t* XH = smu;
  float* c0 = (float*)(smu + XF_U);
  float* c1 = c0 + 9216;
  uint4* W0S = (uint4*)(smu + ZERO_U);
  int tid = threadIdx.x, w = tid >> 5, l = tid & 31;
  int blk = blockIdx.x, base = blk*NP;
  int T = l >> 2, o = w*32 + l;

  for (int i = tid; i < ZERO_U; i += THREADS) smu[i] = 0;
  for (int i = tid; i < W0S_U4; i += THREADS) W0S[i] = g_WF[i];
  __syncthreads();
  stage_seq(seq, base, 0, XH, tid);

  float b1v[4][2];
  #pragma unroll
  for (int g = 0; g < 4; g++)
    #pragma unroll
    for (int hf = 0; hf < 2; hf++){
      int m = g*128 + w*16 + T + 8*hf;
      b1v[g][hf] = __ldg(&bih1[m]) + __ldg(&bhh1[m]);
    }
  __syncthreads();

  const float4* gp = g_gpF + (blk*8 + w)*1152;

  for (int t = 0; t < T_SEQ; t++){
    float acc[36][4];
    #pragma unroll
    for (int g = 0; g < 4; g++)
      #pragma unroll
      for (int nt = 0; nt < 9; nt++){
        float4 v = __ldg(&gp[g*288 + nt*32 + l]);
        acc[g*9+nt][0] = v.x; acc[g*9+nt][1] = v.y;
        acc[g*9+nt][2] = v.z; acc[g*9+nt][3] = v.w;
      }
    gemm_l0(XH, W0S, acc, o, l);
    __syncthreads();
    // prefetch layer-1's first A-frags; latency hidden under epilogue-0
    uint4 a1[4];
    #pragma unroll
    for (int g = 0; g < 4; g++) a1[g] = __ldg(&g_WF[10240 + g*256 + o]);
    epilogue(acc, c0, XH, w, l, 8);
    if (t + 1 < T_SEQ) stage_seq(seq, base, t + 1, XH, tid);
    __syncthreads();

    #pragma unroll
    for (int g = 0; g < 4; g++)
      #pragma unroll
      for (int nt = 0; nt < 9; nt++){
        acc[g*9+nt][0] = b1v[g][0]; acc[g*9+nt][1] = b1v[g][0];
        acc[g*9+nt][2] = b1v[g][1]; acc[g*9+nt][3] = b1v[g][1];
      }
    gemm_l1(XH, acc, o, l, a1);
    __syncthreads();
    epilogue(acc, c1, XH, w, l, 0);
    // no sync needed: h1 slots (0..7) are not read until after two later syncs
  }
  __syncthreads();

  if (tid < NP){
    int a = base + tid;
    if (a < N_NODES){
      float sum = __ldg(fcb);
      int nt = tid >> 3, lanebase = (tid & 7) << 2;
      #pragma unroll 8
      for (int s = 0; s < H; s++){
        int ks = s >> 4, kl = s & 15, r = kl >> 3, cq = (kl & 7) >> 1, hf = kl & 1;
        int ui = ((ks*9 + nt)*32 + lanebase + cq)*2 + r;
        sum += hf2f(((unsigned short*)&XH[ui])[hf]) * __ldg(&fcw[s]);
      }
      out[a] = sum;
    }
  }
}

// ---------------- launch ----------------
extern "C" void kernel_launch(void* const* d_in, const int* in_sizes, int n_in,
                              void* d_out, int out_size){
  const float* seq  = (const float*)d_in[0];
  const void*  ei   = d_in[1];
  const float* nf   = (const float*)d_in[3];
  const float* gw   = (const float*)d_in[5];
  const float* gb   = (const float*)d_in[6];
  const float* wih0 = (const float*)d_in[7];
  const float* whh0 = (const float*)d_in[8];
  const float* bih0 = (const float*)d_in[9];
  const float* bhh0 = (const float*)d_in[10];
  const float* wih1 = (const float*)d_in[11];
  const float* whh1 = (const float*)d_in[12];
  const float* bih1 = (const float*)d_in[13];
  const float* bhh1 = (const float*)d_in[14];
  const float* fcw  = (const float*)d_in[15];
  const float* fcb  = (const float*)d_in[16];
  float* out = (float*)d_out;

  k_reset<<<1,1>>>();
  k_detect<<<64,256>>>((const int*)ei);
  k_init<<<(N_NODES*C_GCN + 255)/256, 256>>>();
  k_degedge<<<(N_EDGES + 255)/256, 256>>>(ei);
  k_xw<<<(N_NODES*C_GCN + 255)/256, 256>>>(nf, gw);
  k_scatter<<<(N_EDGES*64 + 255)/256, 256>>>(ei);
  k_gcnT<<<(N_NODES*C_GCN + 255)/256, 256>>>(gb);
  k_gpf<<<(512*NPAD + 255)/256, 256>>>(wih0, bih0, bhh0);
  k_wf<<<(106496 + 255)/256, 256>>>(wih0, whh0, wih1, whh1);

  cudaFuncSetAttribute(k_mega, cudaFuncAttributeMaxDynamicSharedMemorySize, SMEM_B);
  k_mega<<<NBLK, THREADS, SMEM_B>>>(seq, bih1, bhh1, fcw, fcb, out);
}